// round 2
// baseline (speedup 1.0000x reference)
#include <cuda_runtime.h>
#include <cuda_bf16.h>
#include <math.h>

// Problem constants
#define BB   8
#define LL   2048
#define DD   768
#define ORD  128
#define NFFT 4096
#define MM   (BB*LL)          // 16384
#define N3D  (3*DD)           // 2304

#define MIN_DECAY (-3.0701134573253945f)
#define MAX_DECAY (-15.350567286626972f)

// ---------------- scratch (device globals; no allocations allowed) ------------
__device__ float  g_k[DD * LL];            // filter k[d][l]
__device__ float2 g_Kf[DD * NFFT];         // FFT(k) in DIF (bit-reversed) order
__device__ float2 g_tw[NFFT/2];            // twiddle table exp(-2*pi*i*j/4096)
__device__ float  g_xbuf[(size_t)MM * N3D];// u @ in_W + b   [m][c]
__device__ float  g_vg [BB * DD * LL];     // conv(v)*conv(x1), channel-major
__device__ float  g_x2g[BB * DD * LL];     // conv(x2), channel-major
__device__ float  g_ybT[BB * DD * LL];     // gated fftconv output, channel-major

__device__ __forceinline__ float2 cmul(float2 a, float2 b) {
    return make_float2(a.x*b.x - a.y*b.y, a.x*b.y + a.y*b.x);
}

// ---------------- packed fp32x2 helpers (Blackwell FFMA2) --------------------
__device__ __forceinline__ void ffma2(unsigned long long &c,
                                      unsigned long long a,
                                      unsigned long long b) {
    asm("fma.rn.f32x2 %0, %1, %2, %0;" : "+l"(c) : "l"(a), "l"(b));
}
__device__ __forceinline__ unsigned long long pack2(float x) {
    unsigned long long r;
    asm("mov.b64 %0, {%1, %1};" : "=l"(r) : "f"(x));
    return r;
}
__device__ __forceinline__ void unpack2(unsigned long long v, float &lo, float &hi) {
    asm("mov.b64 {%0, %1}, %2;" : "=f"(lo), "=f"(hi) : "l"(v));
}

// =====================================================================
// Kernel 0: twiddle table
// =====================================================================
__global__ __launch_bounds__(512) void twinit_kernel() {
    const int j = blockIdx.x * 512 + threadIdx.x;
    if (j < NFFT/2) {
        float s, c;
        sincospif(-(float)j / 2048.0f, &s, &c);  // exp(-i*2*pi*j/4096)
        g_tw[j] = make_float2(c, s);
    }
}

// =====================================================================
// Kernel 1: Hyena filter  ->  g_k[d][l]
// =====================================================================
__global__ __launch_bounds__(128) void filter_kernel(
    const float* __restrict__ z,        // [L,5]
    const float* __restrict__ sin_freq, // [128]
    const float* __restrict__ eo_mat,   // [5,128]
    const float* __restrict__ eo_bias,  // [128]
    const float* __restrict__ oo1,      // [128,128]
    const float* __restrict__ oo1_b,
    const float* __restrict__ oo2,
    const float* __restrict__ oo2_b,
    const float* __restrict__ oh)       // [128,768]
{
    __shared__ float hA[16][129];
    __shared__ float hB[16][129];
    const int o  = threadIdx.x;
    const int l0 = blockIdx.x * 16;
    const float f = sin_freq[o];

    #pragma unroll 1
    for (int l = 0; l < 16; l++) {
        float acc = eo_bias[o];
        #pragma unroll
        for (int e = 0; e < 5; e++) acc += z[(l0+l)*5 + e] * eo_mat[e*ORD + o];
        hA[l][o] = sinf(f * acc);
    }
    __syncthreads();
    #pragma unroll 1
    for (int l = 0; l < 16; l++) {
        float acc = oo1_b[o];
        #pragma unroll 4
        for (int p = 0; p < ORD; p++) acc += hA[l][p] * oo1[p*ORD + o];
        hB[l][o] = sinf(f * acc);
    }
    __syncthreads();
    #pragma unroll 1
    for (int l = 0; l < 16; l++) {
        float acc = oo2_b[o];
        #pragma unroll 4
        for (int p = 0; p < ORD; p++) acc += hB[l][p] * oo2[p*ORD + o];
        hA[l][o] = sinf(f * acc);
    }
    __syncthreads();
    #pragma unroll 1
    for (int c = 0; c < DD/ORD; c++) {
        const int d = o + c * ORD;
        float acc[16];
        #pragma unroll
        for (int l = 0; l < 16; l++) acc[l] = 0.f;
        #pragma unroll 2
        for (int p = 0; p < ORD; p++) {
            const float w = oh[p*DD + d];
            #pragma unroll
            for (int l = 0; l < 16; l++) acc[l] += hA[l][p] * w;
        }
        const float delta = fabsf(MIN_DECAY + (MAX_DECAY - MIN_DECAY) * ((float)d / 767.0f));
        #pragma unroll
        for (int l = 0; l < 16; l++) {
            const int lg = l0 + l;
            const float t = (float)lg / 2047.0f;
            g_k[d*LL + lg] = acc[l] * expf(-t * delta);
        }
    }
}

// =====================================================================
// FFT helpers: 4096-pt complex, 512 threads, shared data, tw in smem
// forward = DIF (natural in -> bit-reversed out)
// inverse = DIT w/ conj twiddles (bit-reversed in -> natural out), unscaled
// =====================================================================
__device__ __forceinline__ void copy_tw(float2* tw, int tid) {
    #pragma unroll
    for (int j = tid; j < NFFT/2; j += 512) tw[j] = g_tw[j];
}

__device__ void fft_dif_fwd(float2* data, const float2* tw, int tid) {
    #pragma unroll 1
    for (int s = 11; s >= 0; s--) {
        const int span = 1 << s;
        #pragma unroll
        for (int t = 0; t < 4; t++) {
            const int idx  = tid + t * 512;
            const int j    = idx & (span - 1);
            const int base = ((idx >> s) << (s + 1)) + j;
            const float2 a = data[base];
            const float2 b = data[base + span];
            data[base] = make_float2(a.x + b.x, a.y + b.y);
            const float2 d2 = make_float2(a.x - b.x, a.y - b.y);
            data[base + span] = cmul(d2, tw[j << (11 - s)]);
        }
        __syncthreads();
    }
}

__device__ void fft_dit_inv(float2* data, const float2* tw, int tid) {
    #pragma unroll 1
    for (int s = 0; s <= 11; s++) {
        const int span = 1 << s;
        #pragma unroll
        for (int t = 0; t < 4; t++) {
            const int idx  = tid + t * 512;
            const int j    = idx & (span - 1);
            const int base = ((idx >> s) << (s + 1)) + j;
            float2 w = tw[j << (11 - s)];
            w.y = -w.y;                       // conjugate
            const float2 a = data[base];
            const float2 b = cmul(data[base + span], w);
            data[base]        = make_float2(a.x + b.x, a.y + b.y);
            data[base + span] = make_float2(a.x - b.x, a.y - b.y);
        }
        __syncthreads();
    }
}

// =====================================================================
// Kernel 2: FFT of filter k  ->  g_Kf (bit-reversed order)
// =====================================================================
__global__ __launch_bounds__(512) void fftk_kernel() {
    __shared__ float2 data[NFFT];
    __shared__ float2 tw[NFFT/2];
    const int d = blockIdx.x;
    const int tid = threadIdx.x;
    copy_tw(tw, tid);
    #pragma unroll
    for (int i = tid; i < LL; i += 512) {
        data[i]      = make_float2(g_k[d*LL + i], 0.f);
        data[i + LL] = make_float2(0.f, 0.f);
    }
    __syncthreads();
    fft_dif_fwd(data, tw, tid);
    #pragma unroll
    for (int i = tid; i < NFFT; i += 512) g_Kf[(size_t)d*NFFT + i] = data[i];
}

// =====================================================================
// Kernel 3: GEMM1  C[m][n] = u[m][:] @ in_W + in_b,  M=16384 N=2304 K=768
// 128x128x16 tile, 256 threads, 8x8 per thread via FFMA2, double buffered
// =====================================================================
__global__ __launch_bounds__(256) void gemm1_kernel(
    const float* __restrict__ A, const float* __restrict__ B,
    const float* __restrict__ bias, float* __restrict__ C)
{
    const int K = 768, N = N3D;
    __shared__ __align__(16) float As[2][16][132];
    __shared__ __align__(16) float Bs[2][16][128];
    const int tid = threadIdx.x;
    const int m0 = blockIdx.y * 128;
    const int n0 = blockIdx.x * 128;
    const int tx = tid & 15, ty = tid >> 4;

    const int ar0 = tid >> 2;           // A row within tile (0..63, +64)
    const int ac0 = (tid & 3) * 4;      // A k-col group
    const int br0 = tid >> 5;           // B k-row (0..7, +8)
    const int bc0 = (tid & 31) * 4;     // B n-col group

    unsigned long long acc[8][4];
    #pragma unroll
    for (int i = 0; i < 8; i++)
        #pragma unroll
        for (int j = 0; j < 4; j++) acc[i][j] = 0ull;

    float4 pa[2], pb[2];
    #pragma unroll
    for (int t = 0; t < 2; t++) {
        pa[t] = *reinterpret_cast<const float4*>(&A[(size_t)(m0 + ar0 + t*64)*K + ac0]);
        pb[t] = *reinterpret_cast<const float4*>(&B[(size_t)(br0 + t*8)*N + n0 + bc0]);
    }
    #pragma unroll
    for (int t = 0; t < 2; t++) {
        As[0][ac0+0][ar0+t*64] = pa[t].x;
        As[0][ac0+1][ar0+t*64] = pa[t].y;
        As[0][ac0+2][ar0+t*64] = pa[t].z;
        As[0][ac0+3][ar0+t*64] = pa[t].w;
        *reinterpret_cast<float4*>(&Bs[0][br0+t*8][bc0]) = pb[t];
    }
    __syncthreads();

    const int NT = K / 16;  // 48
    for (int kt = 0; kt < NT; kt++) {
        const int cur = kt & 1;
        if (kt + 1 < NT) {
            const int k0 = (kt + 1) * 16;
            #pragma unroll
            for (int t = 0; t < 2; t++) {
                pa[t] = *reinterpret_cast<const float4*>(&A[(size_t)(m0 + ar0 + t*64)*K + k0 + ac0]);
                pb[t] = *reinterpret_cast<const float4*>(&B[(size_t)(k0 + br0 + t*8)*N + n0 + bc0]);
            }
        }
        #pragma unroll
        for (int kk = 0; kk < 16; kk++) {
            float a[8];
            *reinterpret_cast<float4*>(&a[0]) = *reinterpret_cast<const float4*>(&As[cur][kk][ty*8]);
            *reinterpret_cast<float4*>(&a[4]) = *reinterpret_cast<const float4*>(&As[cur][kk][ty*8+4]);
            const ulonglong2 q0 = *reinterpret_cast<const ulonglong2*>(&Bs[cur][kk][tx*8]);
            const ulonglong2 q1 = *reinterpret_cast<const ulonglong2*>(&Bs[cur][kk][tx*8+4]);
            #pragma unroll
            for (int i = 0; i < 8; i++) {
                const unsigned long long a2 = pack2(a[i]);
                ffma2(acc[i][0], a2, q0.x);
                ffma2(acc[i][1], a2, q0.y);
                ffma2(acc[i][2], a2, q1.x);
                ffma2(acc[i][3], a2, q1.y);
            }
        }
        if (kt + 1 < NT) {
            const int nxt = (kt + 1) & 1;
            #pragma unroll
            for (int t = 0; t < 2; t++) {
                As[nxt][ac0+0][ar0+t*64] = pa[t].x;
                As[nxt][ac0+1][ar0+t*64] = pa[t].y;
                As[nxt][ac0+2][ar0+t*64] = pa[t].z;
                As[nxt][ac0+3][ar0+t*64] = pa[t].w;
                *reinterpret_cast<float4*>(&Bs[nxt][br0+t*8][bc0]) = pb[t];
            }
            __syncthreads();
        }
    }

    #pragma unroll
    for (int i = 0; i < 8; i++) {
        const int m = m0 + ty*8 + i;
        float o[8];
        #pragma unroll
        for (int j2 = 0; j2 < 4; j2++) unpack2(acc[i][j2], o[j2*2], o[j2*2+1]);
        #pragma unroll
        for (int j = 0; j < 8; j += 4) {
            const int n = n0 + tx*8 + j;
            float4 r;
            r.x = o[j+0] + bias[n+0];
            r.y = o[j+1] + bias[n+1];
            r.z = o[j+2] + bias[n+2];
            r.w = o[j+3] + bias[n+3];
            *reinterpret_cast<float4*>(&C[(size_t)m*N + n]) = r;
        }
    }
}

// =====================================================================
// Kernel 3b: depthwise conv-4 (causal) + gating + transpose
// =====================================================================
__global__ __launch_bounds__(256) void convgate_kernel(
    const float* __restrict__ x1_s, const float* __restrict__ x2_s,
    const float* __restrict__ v_s,
    const float* __restrict__ x1_sb, const float* __restrict__ x2_sb,
    const float* __restrict__ v_sb)
{
    __shared__ float sh1[35*33];
    __shared__ float sh2[35*33];
    __shared__ float shv[35*33];
    const int tid = threadIdx.x;
    const int d0 = blockIdx.x * 32;
    const int l0 = blockIdx.y * 32;
    const int b  = blockIdx.z;

    for (int idx = tid; idx < 35*32; idx += 256) {
        const int r  = idx >> 5;
        const int cc = idx & 31;
        const int lg = l0 - 3 + r;
        float v1 = 0.f, v2 = 0.f, vv = 0.f;
        if (lg >= 0) {
            const size_t rowbase = ((size_t)(b*LL + lg)) * N3D + d0 + cc;
            v1 = g_xbuf[rowbase];
            v2 = g_xbuf[rowbase + DD];
            vv = g_xbuf[rowbase + 2*DD];
        }
        sh1[r*33 + cc] = v1;
        sh2[r*33 + cc] = v2;
        shv[r*33 + cc] = vv;
    }
    __syncthreads();

    #pragma unroll
    for (int t = 0; t < 4; t++) {
        const int o  = tid + t*256;
        const int dd = o >> 5;
        const int ll = o & 31;
        const int d  = d0 + dd;
        float c1 = x1_sb[d], c2 = x2_sb[d], cv = v_sb[d];
        #pragma unroll
        for (int j = 0; j < 4; j++) {
            const int r = ll + j;
            c1 += x1_s[d*4 + j] * sh1[r*33 + dd];
            c2 += x2_s[d*4 + j] * sh2[r*33 + dd];
            cv += v_s [d*4 + j] * shv[r*33 + dd];
        }
        const size_t out = ((size_t)(b*DD + d)) * LL + l0 + ll;
        g_vg [out] = cv * c1;
        g_x2g[out] = c2;
    }
}

// =====================================================================
// Kernel 4: per-channel FFT convolution + D_bias + x2 gate
// =====================================================================
__global__ __launch_bounds__(512) void fftconv_kernel(const float* __restrict__ D_bias) {
    __shared__ float2 data[NFFT];
    __shared__ float2 tw[NFFT/2];
    const int bd  = blockIdx.x;          // b*768 + d
    const int d   = bd % DD;
    const int tid = threadIdx.x;
    const size_t ch = (size_t)bd * LL;

    copy_tw(tw, tid);
    float vc[4];
    #pragma unroll
    for (int i = 0; i < 4; i++) {
        const int l = tid + i*512;
        const float v = g_vg[ch + l];
        vc[i] = v;
        data[l]      = make_float2(v, 0.f);
        data[l + LL] = make_float2(0.f, 0.f);
    }
    __syncthreads();

    fft_dif_fwd(data, tw, tid);          // ends with __syncthreads()

    const float2* __restrict__ kf = &g_Kf[(size_t)d * NFFT];
    #pragma unroll
    for (int i = tid; i < NFFT; i += 512) data[i] = cmul(data[i], kf[i]);
    __syncthreads();

    fft_dit_inv(data, tw, tid);          // ends with __syncthreads()

    const float db = D_bias[d];
    #pragma unroll
    for (int i = 0; i < 4; i++) {
        const int l = tid + i*512;
        const float yr = data[l].x * (1.0f / (float)NFFT);
        const float x2 = g_x2g[ch + l];
        g_ybT[ch + l] = (yr + vc[i] * db) * x2;
    }
}

// =====================================================================
// Kernel 5: GEMM2  out[m][n] = ybT^T[m][:] @ out_W + out_b
// A stored channel-major; FFMA2 + double buffering; N=768 K=768
// =====================================================================
__global__ __launch_bounds__(256) void gemm2_kernel(
    const float* __restrict__ B, const float* __restrict__ bias,
    float* __restrict__ C)
{
    const int K = DD, N = DD;
    __shared__ __align__(16) float As[2][16][132];
    __shared__ __align__(16) float Bs[2][16][128];
    const int tid = threadIdx.x;
    const int m0 = blockIdx.y * 128;
    const int n0 = blockIdx.x * 128;
    const int bB = m0 / LL;
    const int l0 = m0 % LL;
    const int tx = tid & 15, ty = tid >> 4;

    const int r0 = tid >> 5;            // k-row (0..7, +8)
    const int c0 = (tid & 31) * 4;      // col group

    unsigned long long acc[8][4];
    #pragma unroll
    for (int i = 0; i < 8; i++)
        #pragma unroll
        for (int j = 0; j < 4; j++) acc[i][j] = 0ull;

    float4 pa[2], pb[2];
    #pragma unroll
    for (int t = 0; t < 2; t++) {
        pa[t] = *reinterpret_cast<const float4*>(&g_ybT[((size_t)(bB*DD + r0 + t*8))*LL + l0 + c0]);
        pb[t] = *reinterpret_cast<const float4*>(&B[(size_t)(r0 + t*8)*N + n0 + c0]);
    }
    #pragma unroll
    for (int t = 0; t < 2; t++) {
        *reinterpret_cast<float4*>(&As[0][r0+t*8][c0]) = pa[t];
        *reinterpret_cast<float4*>(&Bs[0][r0+t*8][c0]) = pb[t];
    }
    __syncthreads();

    const int NT = K / 16;  // 48
    for (int kt = 0; kt < NT; kt++) {
        const int cur = kt & 1;
        if (kt + 1 < NT) {
            const int k0 = (kt + 1) * 16;
            #pragma unroll
            for (int t = 0; t < 2; t++) {
                pa[t] = *reinterpret_cast<const float4*>(&g_ybT[((size_t)(bB*DD + k0 + r0 + t*8))*LL + l0 + c0]);
                pb[t] = *reinterpret_cast<const float4*>(&B[(size_t)(k0 + r0 + t*8)*N + n0 + c0]);
            }
        }
        #pragma unroll
        for (int kk = 0; kk < 16; kk++) {
            float a[8];
            *reinterpret_cast<float4*>(&a[0]) = *reinterpret_cast<const float4*>(&As[cur][kk][ty*8]);
            *reinterpret_cast<float4*>(&a[4]) = *reinterpret_cast<const float4*>(&As[cur][kk][ty*8+4]);
            const ulonglong2 q0 = *reinterpret_cast<const ulonglong2*>(&Bs[cur][kk][tx*8]);
            const ulonglong2 q1 = *reinterpret_cast<const ulonglong2*>(&Bs[cur][kk][tx*8+4]);
            #pragma unroll
            for (int i = 0; i < 8; i++) {
                const unsigned long long a2 = pack2(a[i]);
                ffma2(acc[i][0], a2, q0.x);
                ffma2(acc[i][1], a2, q0.y);
                ffma2(acc[i][2], a2, q1.x);
                ffma2(acc[i][3], a2, q1.y);
            }
        }
        if (kt + 1 < NT) {
            const int nxt = (kt + 1) & 1;
            #pragma unroll
            for (int t = 0; t < 2; t++) {
                *reinterpret_cast<float4*>(&As[nxt][r0+t*8][c0]) = pa[t];
                *reinterpret_cast<float4*>(&Bs[nxt][r0+t*8][c0]) = pb[t];
            }
            __syncthreads();
        }
    }

    #pragma unroll
    for (int i = 0; i < 8; i++) {
        const int m = m0 + ty*8 + i;
        float o[8];
        #pragma unroll
        for (int j2 = 0; j2 < 4; j2++) unpack2(acc[i][j2], o[j2*2], o[j2*2+1]);
        #pragma unroll
        for (int j = 0; j < 8; j += 4) {
            const int n = n0 + tx*8 + j;
            float4 r;
            r.x = o[j+0] + bias[n+0];
            r.y = o[j+1] + bias[n+1];
            r.z = o[j+2] + bias[n+2];
            r.w = o[j+3] + bias[n+3];
            *reinterpret_cast<float4*>(&C[(size_t)m*N + n]) = r;
        }
    }
}

// =====================================================================
// launch
// =====================================================================
extern "C" void kernel_launch(void* const* d_in, const int* in_sizes, int n_in,
                              void* d_out, int out_size) {
    const float* u      = (const float*)d_in[0];
    const float* in_W   = (const float*)d_in[1];
    const float* in_b   = (const float*)d_in[2];
    const float* out_W  = (const float*)d_in[3];
    const float* out_b  = (const float*)d_in[4];
    const float* x1_s   = (const float*)d_in[5];
    const float* x2_s   = (const float*)d_in[6];
    const float* v_s    = (const float*)d_in[7];
    const float* x1_sb  = (const float*)d_in[8];
    const float* x2_sb  = (const float*)d_in[9];
    const float* v_sb   = (const float*)d_in[10];
    const float* D_bias = (const float*)d_in[11];
    const float* z      = (const float*)d_in[12];
    const float* sfreq  = (const float*)d_in[13];
    const float* eo_mat = (const float*)d_in[14];
    const float* eo_b   = (const float*)d_in[15];
    const float* oo1    = (const float*)d_in[16];
    const float* oo1_b  = (const float*)d_in[17];
    const float* oo2    = (const float*)d_in[18];
    const float* oo2_b  = (const float*)d_in[19];
    const float* oh     = (const float*)d_in[20];
    float* out = (float*)d_out;

    twinit_kernel<<<4, 512>>>();
    filter_kernel<<<LL/16, 128>>>(z, sfreq, eo_mat, eo_b, oo1, oo1_b, oo2, oo2_b, oh);
    fftk_kernel<<<DD, 512>>>();

    float* xbuf;
    cudaGetSymbolAddress((void**)&xbuf, g_xbuf);
    gemm1_kernel<<<dim3(N3D/128, MM/128), 256>>>(u, in_W, in_b, xbuf);

    convgate_kernel<<<dim3(DD/32, LL/32, BB), 256>>>(x1_s, x2_s, v_s, x1_sb, x2_sb, v_sb);
    fftconv_kernel<<<BB*DD, 512>>>(D_bias);
    gemm2_kernel<<<dim3(DD/128, MM/128), 256>>>(out_W, out_b, out);
}

// round 4
// speedup vs baseline: 1.4057x; 1.4057x over previous
#include <cuda_runtime.h>
#include <cuda_bf16.h>
#include <math.h>
#include <stdint.h>

// Problem constants
#define BB   8
#define LL   2048
#define DD   768
#define ORD  128
#define NFFT 4096
#define MM   (BB*LL)          // 16384
#define N3D  (3*DD)           // 2304

#define MIN_DECAY (-3.0701134573253945f)
#define MAX_DECAY (-15.350567286626972f)

// ---------------- scratch (device globals; no allocations allowed) ------------
__device__ float  g_k[DD * LL];            // filter k[d][l]
__device__ float2 g_Kf[DD * NFFT];         // FFT(k) in DIF (bit-reversed) order
__device__ float2 g_tw[NFFT/2];            // twiddle table exp(-2*pi*i*j/4096)
__device__ float  g_xbuf[(size_t)MM * N3D];// u @ in_W + b   [m][c]
__device__ float  g_vg [BB * DD * LL];     // conv(v)*conv(x1), channel-major
__device__ float  g_x2g[BB * DD * LL];     // conv(x2), channel-major
__device__ float  g_ybT[BB * DD * LL];     // gated fftconv output, channel-major

// bf16 split operands for tensor-core GEMMs
__device__ __nv_bfloat16 g_uh[(size_t)MM * DD];
__device__ __nv_bfloat16 g_ul[(size_t)MM * DD];
__device__ __nv_bfloat16 g_wh[(size_t)N3D * DD];   // in_W^T  [N][K]
__device__ __nv_bfloat16 g_wl[(size_t)N3D * DD];
__device__ __nv_bfloat16 g_woh[(size_t)DD * DD];   // out_W^T [N][K]
__device__ __nv_bfloat16 g_wol[(size_t)DD * DD];
__device__ __nv_bfloat16 g_yh[(size_t)MM * DD];    // gated y  [m][k]
__device__ __nv_bfloat16 g_yl[(size_t)MM * DD];

__device__ __forceinline__ float2 cmul(float2 a, float2 b) {
    return make_float2(a.x*b.x - a.y*b.y, a.x*b.y + a.y*b.x);
}

// ============================ mma helpers ====================================
__device__ __forceinline__ uint32_t smem_u32(const void* p) {
    uint32_t a;
    asm("{ .reg .u64 t; cvta.to.shared.u64 t, %1; cvt.u32.u64 %0, t; }" : "=r"(a) : "l"(p));
    return a;
}
__device__ __forceinline__ void ldmatrix_x4(uint32_t &r0, uint32_t &r1,
                                            uint32_t &r2, uint32_t &r3,
                                            uint32_t addr) {
    asm volatile("ldmatrix.sync.aligned.m8n8.x4.shared.b16 {%0,%1,%2,%3}, [%4];"
                 : "=r"(r0), "=r"(r1), "=r"(r2), "=r"(r3) : "r"(addr));
}
__device__ __forceinline__ void mma16816(float* c,
                                         uint32_t a0, uint32_t a1, uint32_t a2, uint32_t a3,
                                         uint32_t b0, uint32_t b1) {
    asm volatile("mma.sync.aligned.m16n8k16.row.col.f32.bf16.bf16.f32 "
                 "{%0,%1,%2,%3}, {%4,%5,%6,%7}, {%8,%9}, {%0,%1,%2,%3};"
                 : "+f"(c[0]), "+f"(c[1]), "+f"(c[2]), "+f"(c[3])
                 : "r"(a0), "r"(a1), "r"(a2), "r"(a3), "r"(b0), "r"(b1));
}

// =====================================================================
// Kernel 0: twiddle table
// =====================================================================
__global__ __launch_bounds__(512) void twinit_kernel() {
    const int j = blockIdx.x * 512 + threadIdx.x;
    if (j < NFFT/2) {
        float s, c;
        sincospif(-(float)j / 2048.0f, &s, &c);
        g_tw[j] = make_float2(c, s);
    }
}

// =====================================================================
// Kernel 1: Hyena filter  ->  g_k[d][l]
// =====================================================================
__global__ __launch_bounds__(128) void filter_kernel(
    const float* __restrict__ z, const float* __restrict__ sin_freq,
    const float* __restrict__ eo_mat, const float* __restrict__ eo_bias,
    const float* __restrict__ oo1, const float* __restrict__ oo1_b,
    const float* __restrict__ oo2, const float* __restrict__ oo2_b,
    const float* __restrict__ oh)
{
    __shared__ float hA[16][129];
    __shared__ float hB[16][129];
    const int o  = threadIdx.x;
    const int l0 = blockIdx.x * 16;
    const float f = sin_freq[o];

    #pragma unroll 1
    for (int l = 0; l < 16; l++) {
        float acc = eo_bias[o];
        #pragma unroll
        for (int e = 0; e < 5; e++) acc += z[(l0+l)*5 + e] * eo_mat[e*ORD + o];
        hA[l][o] = sinf(f * acc);
    }
    __syncthreads();
    #pragma unroll 1
    for (int l = 0; l < 16; l++) {
        float acc = oo1_b[o];
        #pragma unroll 4
        for (int p = 0; p < ORD; p++) acc += hA[l][p] * oo1[p*ORD + o];
        hB[l][o] = sinf(f * acc);
    }
    __syncthreads();
    #pragma unroll 1
    for (int l = 0; l < 16; l++) {
        float acc = oo2_b[o];
        #pragma unroll 4
        for (int p = 0; p < ORD; p++) acc += hB[l][p] * oo2[p*ORD + o];
        hA[l][o] = sinf(f * acc);
    }
    __syncthreads();
    #pragma unroll 1
    for (int c = 0; c < DD/ORD; c++) {
        const int d = o + c * ORD;
        float acc[16];
        #pragma unroll
        for (int l = 0; l < 16; l++) acc[l] = 0.f;
        #pragma unroll 2
        for (int p = 0; p < ORD; p++) {
            const float w = oh[p*DD + d];
            #pragma unroll
            for (int l = 0; l < 16; l++) acc[l] += hA[l][p] * w;
        }
        const float delta = fabsf(MIN_DECAY + (MAX_DECAY - MIN_DECAY) * ((float)d / 767.0f));
        #pragma unroll
        for (int l = 0; l < 16; l++) {
            const int lg = l0 + l;
            const float t = (float)lg / 2047.0f;
            g_k[d*LL + lg] = acc[l] * expf(-t * delta);
        }
    }
}

// =====================================================================
// FFT helpers (512 threads per CTA)
// =====================================================================
__device__ __forceinline__ void copy_tw(float2* tw, int tid) {
    #pragma unroll
    for (int j = tid; j < NFFT/2; j += 512) tw[j] = g_tw[j];
}

__device__ void fft_dif_fwd(float2* data, const float2* tw, int tid) {
    #pragma unroll 1
    for (int s = 11; s >= 0; s--) {
        const int span = 1 << s;
        #pragma unroll
        for (int t = 0; t < 4; t++) {
            const int idx  = tid + t * 512;
            const int j    = idx & (span - 1);
            const int base = ((idx >> s) << (s + 1)) + j;
            const float2 a = data[base];
            const float2 b = data[base + span];
            data[base] = make_float2(a.x + b.x, a.y + b.y);
            const float2 d2 = make_float2(a.x - b.x, a.y - b.y);
            data[base + span] = cmul(d2, tw[j << (11 - s)]);
        }
        __syncthreads();
    }
}

__device__ void fft_dit_inv(float2* data, const float2* tw, int tid) {
    #pragma unroll 1
    for (int s = 0; s <= 11; s++) {
        const int span = 1 << s;
        #pragma unroll
        for (int t = 0; t < 4; t++) {
            const int idx  = tid + t * 512;
            const int j    = idx & (span - 1);
            const int base = ((idx >> s) << (s + 1)) + j;
            float2 w = tw[j << (11 - s)];
            w.y = -w.y;
            const float2 a = data[base];
            const float2 b = cmul(data[base + span], w);
            data[base]        = make_float2(a.x + b.x, a.y + b.y);
            data[base + span] = make_float2(a.x - b.x, a.y - b.y);
        }
        __syncthreads();
    }
}

// =====================================================================
// Kernel 2: FFT of filter k  ->  g_Kf
// =====================================================================
__global__ __launch_bounds__(512) void fftk_kernel() {
    __shared__ float2 data[NFFT];
    __shared__ float2 tw[NFFT/2];
    const int d = blockIdx.x;
    const int tid = threadIdx.x;
    copy_tw(tw, tid);
    #pragma unroll
    for (int i = tid; i < LL; i += 512) {
        data[i]      = make_float2(g_k[d*LL + i], 0.f);
        data[i + LL] = make_float2(0.f, 0.f);
    }
    __syncthreads();
    fft_dif_fwd(data, tw, tid);
    #pragma unroll
    for (int i = tid; i < NFFT; i += 512) g_Kf[(size_t)d*NFFT + i] = data[i];
}

// =====================================================================
// Prep: split fp32 -> bf16 hi/lo (same layout)
// =====================================================================
__global__ __launch_bounds__(256) void split_kernel(
    const float* __restrict__ in, __nv_bfloat16* __restrict__ oh,
    __nv_bfloat16* __restrict__ ol, int n4)
{
    const int i = blockIdx.x * 256 + threadIdx.x;
    if (i >= n4) return;
    const float4 v = reinterpret_cast<const float4*>(in)[i];
    __nv_bfloat16 h0 = __float2bfloat16(v.x), h1 = __float2bfloat16(v.y);
    __nv_bfloat16 h2 = __float2bfloat16(v.z), h3 = __float2bfloat16(v.w);
    __nv_bfloat16 l0 = __float2bfloat16(v.x - __bfloat162float(h0));
    __nv_bfloat16 l1 = __float2bfloat16(v.y - __bfloat162float(h1));
    __nv_bfloat16 l2 = __float2bfloat16(v.z - __bfloat162float(h2));
    __nv_bfloat16 l3 = __float2bfloat16(v.w - __bfloat162float(h3));
    reinterpret_cast<__nv_bfloat162*>(oh)[i*2]   = __nv_bfloat162(h0, h1);
    reinterpret_cast<__nv_bfloat162*>(oh)[i*2+1] = __nv_bfloat162(h2, h3);
    reinterpret_cast<__nv_bfloat162*>(ol)[i*2]   = __nv_bfloat162(l0, l1);
    reinterpret_cast<__nv_bfloat162*>(ol)[i*2+1] = __nv_bfloat162(l2, l3);
}

// =====================================================================
// Prep: transpose [R][C] fp32 -> [C][R] bf16 hi/lo (with batch)
// =====================================================================
__global__ __launch_bounds__(256) void transpose_split_kernel(
    const float* __restrict__ in, __nv_bfloat16* __restrict__ oh,
    __nv_bfloat16* __restrict__ ol, int R, int C,
    size_t inBatch, size_t outBatch)
{
    __shared__ float tile[32][33];
    const int b  = blockIdx.z;
    const float* src = in + (size_t)b * inBatch;
    const int r0 = blockIdx.y * 32, c0 = blockIdx.x * 32;
    const int tx = threadIdx.x & 31, ty = threadIdx.x >> 5;
    #pragma unroll
    for (int i = 0; i < 32; i += 8)
        tile[ty+i][tx] = src[(size_t)(r0+ty+i)*C + c0 + tx];
    __syncthreads();
    #pragma unroll
    for (int i = 0; i < 32; i += 8) {
        const float x = tile[tx][ty+i];
        const __nv_bfloat16 h = __float2bfloat16(x);
        const __nv_bfloat16 l = __float2bfloat16(x - __bfloat162float(h));
        const size_t o = (size_t)b*outBatch + (size_t)(c0+ty+i)*R + r0 + tx;
        oh[o] = h;
        ol[o] = l;
    }
}

// =====================================================================
// mma.sync GEMM: C[M][N] = A[M][K] @ B[N][K]^T + bias
// A,B bf16 hi/lo; fp32 emulation: Ah*Bh + Ah*Bl + Al*Bh.
// CTA tile 128x128, 8 warps (warp tile 32m x 64n), K-chunks of 16.
// =====================================================================
#define AS_STRIDE 24   // bf16 elems per smem row (16 data + 8 pad)

__global__ __launch_bounds__(256, 2) void gemm_mma_kernel(
    const __nv_bfloat16* __restrict__ Ah, const __nv_bfloat16* __restrict__ Al,
    const __nv_bfloat16* __restrict__ Bh, const __nv_bfloat16* __restrict__ Bl,
    const float* __restrict__ bias, float* __restrict__ C,
    int K, int N)
{
    __shared__ __align__(16) __nv_bfloat16 AsH[128*AS_STRIDE];
    __shared__ __align__(16) __nv_bfloat16 AsL[128*AS_STRIDE];
    __shared__ __align__(16) __nv_bfloat16 BsH[128*AS_STRIDE];
    __shared__ __align__(16) __nv_bfloat16 BsL[128*AS_STRIDE];

    const int tid  = threadIdx.x;
    const int wid  = tid >> 5;
    const int lane = tid & 31;
    const int m0 = blockIdx.y * 128;
    const int n0 = blockIdx.x * 128;
    const int wm = (wid & 3) * 32;   // warp m offset in tile
    const int wn = (wid >> 2) * 64;  // warp n offset in tile

    // global load mapping: each thread one uint4 (8 bf16) per array
    const int lrow = tid >> 1;          // 0..127
    const int lseg = (tid & 1) * 8;     // 0 or 8 (k offset)

    // ldmatrix addresses (constant across chunks; single smem buffer)
    const uint32_t asAh = smem_u32(AsH), asAl = smem_u32(AsL);
    const uint32_t asBh = smem_u32(BsH), asBl = smem_u32(BsL);
    const int arow  = wm + (lane & 15);
    const uint32_t akoff = (uint32_t)(lane >> 4) * 16;
    const uint32_t aoffs = (uint32_t)arow * (AS_STRIDE*2) + akoff;
    const uint32_t aH0 = asAh + aoffs;
    const uint32_t aH1 = aH0 + 16*AS_STRIDE*2;
    const uint32_t aL0 = asAl + aoffs;
    const uint32_t aL1 = aL0 + 16*AS_STRIDE*2;
    const int brow  = wn + (lane & 7) + ((lane >> 4) & 1) * 8;
    const uint32_t bkoff = (uint32_t)((lane >> 3) & 1) * 16;
    const uint32_t boffs = (uint32_t)brow * (AS_STRIDE*2) + bkoff;

    float acc[2][8][4];
    #pragma unroll
    for (int i = 0; i < 2; i++)
        #pragma unroll
        for (int j = 0; j < 8; j++)
            #pragma unroll
            for (int q = 0; q < 4; q++) acc[i][j][q] = 0.f;

    uint4 rAh, rAl, rBh, rBl;
    const int NKB = K >> 4;   // 48

    // prologue: chunk 0 -> regs -> smem
    {
        const size_t offA = (size_t)(m0 + lrow)*K + lseg;
        const size_t offB = (size_t)(n0 + lrow)*K + lseg;
        rAh = *reinterpret_cast<const uint4*>(Ah + offA);
        rAl = *reinterpret_cast<const uint4*>(Al + offA);
        rBh = *reinterpret_cast<const uint4*>(Bh + offB);
        rBl = *reinterpret_cast<const uint4*>(Bl + offB);
        const uint32_t so = (uint32_t)lrow*AS_STRIDE + lseg;
        *reinterpret_cast<uint4*>(&AsH[so]) = rAh;
        *reinterpret_cast<uint4*>(&AsL[so]) = rAl;
        *reinterpret_cast<uint4*>(&BsH[so]) = rBh;
        *reinterpret_cast<uint4*>(&BsL[so]) = rBl;
    }
    __syncthreads();

    for (int kb = 0; kb < NKB; kb++) {
        // prefetch next chunk from gmem (overlaps with mma below)
        if (kb + 1 < NKB) {
            const int k0 = (kb + 1) * 16;
            const size_t offA = (size_t)(m0 + lrow)*K + k0 + lseg;
            const size_t offB = (size_t)(n0 + lrow)*K + k0 + lseg;
            rAh = *reinterpret_cast<const uint4*>(Ah + offA);
            rAl = *reinterpret_cast<const uint4*>(Al + offA);
            rBh = *reinterpret_cast<const uint4*>(Bh + offB);
            rBl = *reinterpret_cast<const uint4*>(Bl + offB);
        }

        // A fragments (2 m-tiles, hi+lo)
        uint32_t ah[2][4], al[2][4];
        ldmatrix_x4(ah[0][0], ah[0][1], ah[0][2], ah[0][3], aH0);
        ldmatrix_x4(ah[1][0], ah[1][1], ah[1][2], ah[1][3], aH1);
        ldmatrix_x4(al[0][0], al[0][1], al[0][2], al[0][3], aL0);
        ldmatrix_x4(al[1][0], al[1][1], al[1][2], al[1][3], aL1);

        // B fragments per pair of n-tiles, then mma
        #pragma unroll
        for (int p = 0; p < 4; p++) {
            uint32_t bh0, bh1, bh2, bh3, bl0, bl1, bl2, bl3;
            const uint32_t bo = boffs + (uint32_t)p * (16*AS_STRIDE*2);
            ldmatrix_x4(bh0, bh1, bh2, bh3, asBh + bo);
            ldmatrix_x4(bl0, bl1, bl2, bl3, asBl + bo);
            #pragma unroll
            for (int mt = 0; mt < 2; mt++) {
                // n-tile 2p
                mma16816(acc[mt][2*p],   ah[mt][0], ah[mt][1], ah[mt][2], ah[mt][3], bh0, bh1);
                mma16816(acc[mt][2*p],   ah[mt][0], ah[mt][1], ah[mt][2], ah[mt][3], bl0, bl1);
                mma16816(acc[mt][2*p],   al[mt][0], al[mt][1], al[mt][2], al[mt][3], bh0, bh1);
                // n-tile 2p+1
                mma16816(acc[mt][2*p+1], ah[mt][0], ah[mt][1], ah[mt][2], ah[mt][3], bh2, bh3);
                mma16816(acc[mt][2*p+1], ah[mt][0], ah[mt][1], ah[mt][2], ah[mt][3], bl2, bl3);
                mma16816(acc[mt][2*p+1], al[mt][0], al[mt][1], al[mt][2], al[mt][3], bh2, bh3);
            }
        }

        __syncthreads();
        if (kb + 1 < NKB) {
            const uint32_t so = (uint32_t)lrow*AS_STRIDE + lseg;
            *reinterpret_cast<uint4*>(&AsH[so]) = rAh;
            *reinterpret_cast<uint4*>(&AsL[so]) = rAl;
            *reinterpret_cast<uint4*>(&BsH[so]) = rBh;
            *reinterpret_cast<uint4*>(&BsL[so]) = rBl;
            __syncthreads();
        }
    }

    // epilogue: fragment layout -> gmem with bias
    const int crow = lane >> 2;
    const int ccol = (lane & 3) * 2;
    #pragma unroll
    for (int mt = 0; mt < 2; mt++) {
        const int mbase = m0 + wm + mt*16 + crow;
        #pragma unroll
        for (int nt = 0; nt < 8; nt++) {
            const int n = n0 + wn + nt*8 + ccol;
            const float b0 = bias[n], b1 = bias[n+1];
            float2 r0 = make_float2(acc[mt][nt][0] + b0, acc[mt][nt][1] + b1);
            float2 r1 = make_float2(acc[mt][nt][2] + b0, acc[mt][nt][3] + b1);
            *reinterpret_cast<float2*>(&C[(size_t)mbase*N + n])     = r0;
            *reinterpret_cast<float2*>(&C[(size_t)(mbase+8)*N + n]) = r1;
        }
    }
}

// =====================================================================
// depthwise conv-4 (causal) + gating + transpose
// =====================================================================
__global__ __launch_bounds__(256) void convgate_kernel(
    const float* __restrict__ x1_s, const float* __restrict__ x2_s,
    const float* __restrict__ v_s,
    const float* __restrict__ x1_sb, const float* __restrict__ x2_sb,
    const float* __restrict__ v_sb)
{
    __shared__ float sh1[35*33];
    __shared__ float sh2[35*33];
    __shared__ float shv[35*33];
    const int tid = threadIdx.x;
    const int d0 = blockIdx.x * 32;
    const int l0 = blockIdx.y * 32;
    const int b  = blockIdx.z;

    for (int idx = tid; idx < 35*32; idx += 256) {
        const int r  = idx >> 5;
        const int cc = idx & 31;
        const int lg = l0 - 3 + r;
        float v1 = 0.f, v2 = 0.f, vv = 0.f;
        if (lg >= 0) {
            const size_t rowbase = ((size_t)(b*LL + lg)) * N3D + d0 + cc;
            v1 = g_xbuf[rowbase];
            v2 = g_xbuf[rowbase + DD];
            vv = g_xbuf[rowbase + 2*DD];
        }
        sh1[r*33 + cc] = v1;
        sh2[r*33 + cc] = v2;
        shv[r*33 + cc] = vv;
    }
    __syncthreads();

    #pragma unroll
    for (int t = 0; t < 4; t++) {
        const int o  = tid + t*256;
        const int dd = o >> 5;
        const int ll = o & 31;
        const int d  = d0 + dd;
        float c1 = x1_sb[d], c2 = x2_sb[d], cv = v_sb[d];
        #pragma unroll
        for (int j = 0; j < 4; j++) {
            const int r = ll + j;
            c1 += x1_s[d*4 + j] * sh1[r*33 + dd];
            c2 += x2_s[d*4 + j] * sh2[r*33 + dd];
            cv += v_s [d*4 + j] * shv[r*33 + dd];
        }
        const size_t out = ((size_t)(b*DD + d)) * LL + l0 + ll;
        g_vg [out] = cv * c1;
        g_x2g[out] = c2;
    }
}

// =====================================================================
// per-channel FFT convolution + D_bias + x2 gate
// =====================================================================
__global__ __launch_bounds__(512) void fftconv_kernel(const float* __restrict__ D_bias) {
    __shared__ float2 data[NFFT];
    __shared__ float2 tw[NFFT/2];
    const int bd  = blockIdx.x;
    const int d   = bd % DD;
    const int tid = threadIdx.x;
    const size_t ch = (size_t)bd * LL;

    copy_tw(tw, tid);
    float vc[4];
    #pragma unroll
    for (int i = 0; i < 4; i++) {
        const int l = tid + i*512;
        const float v = g_vg[ch + l];
        vc[i] = v;
        data[l]      = make_float2(v, 0.f);
        data[l + LL] = make_float2(0.f, 0.f);
    }
    __syncthreads();

    fft_dif_fwd(data, tw, tid);

    const float2* __restrict__ kf = &g_Kf[(size_t)d * NFFT];
    #pragma unroll
    for (int i = tid; i < NFFT; i += 512) data[i] = cmul(data[i], kf[i]);
    __syncthreads();

    fft_dit_inv(data, tw, tid);

    const float db = D_bias[d];
    #pragma unroll
    for (int i = 0; i < 4; i++) {
        const int l = tid + i*512;
        const float yr = data[l].x * (1.0f / (float)NFFT);
        const float x2 = g_x2g[ch + l];
        g_ybT[ch + l] = (yr + vc[i] * db) * x2;
    }
}

// =====================================================================
// launch
// =====================================================================
extern "C" void kernel_launch(void* const* d_in, const int* in_sizes, int n_in,
                              void* d_out, int out_size) {
    const float* u      = (const float*)d_in[0];
    const float* in_W   = (const float*)d_in[1];
    const float* in_b   = (const float*)d_in[2];
    const float* out_W  = (const float*)d_in[3];
    const float* out_b  = (const float*)d_in[4];
    const float* x1_s   = (const float*)d_in[5];
    const float* x2_s   = (const float*)d_in[6];
    const float* v_s    = (const float*)d_in[7];
    const float* x1_sb  = (const float*)d_in[8];
    const float* x2_sb  = (const float*)d_in[9];
    const float* v_sb   = (const float*)d_in[10];
    const float* D_bias = (const float*)d_in[11];
    const float* z      = (const float*)d_in[12];
    const float* sfreq  = (const float*)d_in[13];
    const float* eo_mat = (const float*)d_in[14];
    const float* eo_b   = (const float*)d_in[15];
    const float* oo1    = (const float*)d_in[16];
    const float* oo1_b  = (const float*)d_in[17];
    const float* oo2    = (const float*)d_in[18];
    const float* oo2_b  = (const float*)d_in[19];
    const float* oh     = (const float*)d_in[20];
    float* out = (float*)d_out;

    float *xbuf, *ybT;
    __nv_bfloat16 *uh, *ul, *wh, *wl, *woh, *wol, *yh, *yl;
    cudaGetSymbolAddress((void**)&xbuf, g_xbuf);
    cudaGetSymbolAddress((void**)&ybT,  g_ybT);
    cudaGetSymbolAddress((void**)&uh,  g_uh);
    cudaGetSymbolAddress((void**)&ul,  g_ul);
    cudaGetSymbolAddress((void**)&wh,  g_wh);
    cudaGetSymbolAddress((void**)&wl,  g_wl);
    cudaGetSymbolAddress((void**)&woh, g_woh);
    cudaGetSymbolAddress((void**)&wol, g_wol);
    cudaGetSymbolAddress((void**)&yh,  g_yh);
    cudaGetSymbolAddress((void**)&yl,  g_yl);

    // filter + its FFT
    twinit_kernel<<<4, 512>>>();
    filter_kernel<<<LL/16, 128>>>(z, sfreq, eo_mat, eo_b, oo1, oo1_b, oo2, oo2_b, oh);
    fftk_kernel<<<DD, 512>>>();

    // bf16 split preps
    split_kernel<<<(MM*DD/4 + 255)/256, 256>>>(u, uh, ul, MM*DD/4);
    transpose_split_kernel<<<dim3(N3D/32, DD/32, 1), 256>>>(in_W,  wh,  wl,  DD, N3D, 0, 0);
    transpose_split_kernel<<<dim3(DD/32,  DD/32, 1), 256>>>(out_W, woh, wol, DD, DD,  0, 0);

    // GEMM1: [16384 x 768] @ [768 x 2304]
    gemm_mma_kernel<<<dim3(N3D/128, MM/128), 256>>>(uh, ul, wh, wl, in_b, xbuf, DD, N3D);

    convgate_kernel<<<dim3(DD/32, LL/32, BB), 256>>>(x1_s, x2_s, v_s, x1_sb, x2_sb, v_sb);
    fftconv_kernel<<<BB*DD, 512>>>(D_bias);

    // transpose gated output [b][d][l] -> [(b,l)][d] bf16 hi/lo
    transpose_split_kernel<<<dim3(LL/32, DD/32, BB), 256>>>(
        ybT, yh, yl, DD, LL, (size_t)DD*LL, (size_t)DD*LL);

    // GEMM2: [16384 x 768] @ [768 x 768]
    gemm_mma_kernel<<<dim3(DD/128, MM/128), 256>>>(yh, yl, woh, wol, out_b, out, DD, DD);
}

// round 6
// speedup vs baseline: 1.4537x; 1.0342x over previous
#include <cuda_runtime.h>
#include <cuda_bf16.h>
#include <math.h>
#include <stdint.h>

// Problem constants
#define BB   8
#define LL   2048
#define DD   768
#define ORD  128
#define NFFT 4096
#define MM   (BB*LL)          // 16384
#define N3D  (3*DD)           // 2304

#define MIN_DECAY (-3.0701134573253945f)
#define MAX_DECAY (-15.350567286626972f)

// ---------------- scratch (device globals; no allocations allowed) ------------
__device__ float  g_k[DD * LL];            // filter k[d][l]
__device__ float2 g_Kf[DD * NFFT];         // FFT(k) in DIF (bit-reversed) order
__device__ float2 g_tw[NFFT/2];            // twiddle table exp(-2*pi*i*j/4096)
__device__ float  g_xbuf[(size_t)MM * N3D];// u @ in_W + b   [m][c]
__device__ float  g_vg [BB * DD * LL];     // conv(v)*conv(x1), channel-major
__device__ float  g_x2g[BB * DD * LL];     // conv(x2), channel-major
__device__ float  g_ybT[BB * DD * LL];     // gated fftconv output, channel-major

// bf16 split operands for tensor-core GEMMs
__device__ __nv_bfloat16 g_uh[(size_t)MM * DD];
__device__ __nv_bfloat16 g_ul[(size_t)MM * DD];
__device__ __nv_bfloat16 g_wh[(size_t)N3D * DD];   // in_W^T  [N][K]
__device__ __nv_bfloat16 g_wl[(size_t)N3D * DD];
__device__ __nv_bfloat16 g_woh[(size_t)DD * DD];   // out_W^T [N][K]
__device__ __nv_bfloat16 g_wol[(size_t)DD * DD];
__device__ __nv_bfloat16 g_yh[(size_t)MM * DD];    // gated y  [m][k]
__device__ __nv_bfloat16 g_yl[(size_t)MM * DD];

__device__ __forceinline__ float2 cmul(float2 a, float2 b) {
    return make_float2(a.x*b.x - a.y*b.y, a.x*b.y + a.y*b.x);
}

// ============================ mma helpers ====================================
__device__ __forceinline__ uint32_t smem_u32(const void* p) {
    uint32_t a;
    asm("{ .reg .u64 t; cvta.to.shared.u64 t, %1; cvt.u32.u64 %0, t; }" : "=r"(a) : "l"(p));
    return a;
}
__device__ __forceinline__ void ldmatrix_x4(uint32_t &r0, uint32_t &r1,
                                            uint32_t &r2, uint32_t &r3,
                                            uint32_t addr) {
    asm volatile("ldmatrix.sync.aligned.m8n8.x4.shared.b16 {%0,%1,%2,%3}, [%4];"
                 : "=r"(r0), "=r"(r1), "=r"(r2), "=r"(r3) : "r"(addr));
}
__device__ __forceinline__ void mma16816(float* c,
                                         uint32_t a0, uint32_t a1, uint32_t a2, uint32_t a3,
                                         uint32_t b0, uint32_t b1) {
    asm volatile("mma.sync.aligned.m16n8k16.row.col.f32.bf16.bf16.f32 "
                 "{%0,%1,%2,%3}, {%4,%5,%6,%7}, {%8,%9}, {%0,%1,%2,%3};"
                 : "+f"(c[0]), "+f"(c[1]), "+f"(c[2]), "+f"(c[3])
                 : "r"(a0), "r"(a1), "r"(a2), "r"(a3), "r"(b0), "r"(b1));
}
#define CP_ASYNC16(dst, src) \
    asm volatile("cp.async.cg.shared.global [%0], [%1], 16;" :: "r"(dst), "l"(src))
#define CP_COMMIT() asm volatile("cp.async.commit_group;" ::: "memory")
template<int N>
__device__ __forceinline__ void cp_wait() {
    asm volatile("cp.async.wait_group %0;" :: "n"(N) : "memory");
}

// =====================================================================
// Kernel 0: twiddle table
// =====================================================================
__global__ __launch_bounds__(512) void twinit_kernel() {
    const int j = blockIdx.x * 512 + threadIdx.x;
    if (j < NFFT/2) {
        float s, c;
        sincospif(-(float)j / 2048.0f, &s, &c);
        g_tw[j] = make_float2(c, s);
    }
}

// =====================================================================
// Kernel 1: Hyena filter  ->  g_k[d][l]
// =====================================================================
__global__ __launch_bounds__(128) void filter_kernel(
    const float* __restrict__ z, const float* __restrict__ sin_freq,
    const float* __restrict__ eo_mat, const float* __restrict__ eo_bias,
    const float* __restrict__ oo1, const float* __restrict__ oo1_b,
    const float* __restrict__ oo2, const float* __restrict__ oo2_b,
    const float* __restrict__ oh)
{
    __shared__ float hA[16][129];
    __shared__ float hB[16][129];
    const int o  = threadIdx.x;
    const int l0 = blockIdx.x * 16;
    const float f = sin_freq[o];

    #pragma unroll 1
    for (int l = 0; l < 16; l++) {
        float acc = eo_bias[o];
        #pragma unroll
        for (int e = 0; e < 5; e++) acc += z[(l0+l)*5 + e] * eo_mat[e*ORD + o];
        hA[l][o] = sinf(f * acc);
    }
    __syncthreads();
    #pragma unroll 1
    for (int l = 0; l < 16; l++) {
        float acc = oo1_b[o];
        #pragma unroll 4
        for (int p = 0; p < ORD; p++) acc += hA[l][p] * oo1[p*ORD + o];
        hB[l][o] = sinf(f * acc);
    }
    __syncthreads();
    #pragma unroll 1
    for (int l = 0; l < 16; l++) {
        float acc = oo2_b[o];
        #pragma unroll 4
        for (int p = 0; p < ORD; p++) acc += hB[l][p] * oo2[p*ORD + o];
        hA[l][o] = sinf(f * acc);
    }
    __syncthreads();
    #pragma unroll 1
    for (int c = 0; c < DD/ORD; c++) {
        const int d = o + c * ORD;
        float acc[16];
        #pragma unroll
        for (int l = 0; l < 16; l++) acc[l] = 0.f;
        #pragma unroll 2
        for (int p = 0; p < ORD; p++) {
            const float w = oh[p*DD + d];
            #pragma unroll
            for (int l = 0; l < 16; l++) acc[l] += hA[l][p] * w;
        }
        const float delta = fabsf(MIN_DECAY + (MAX_DECAY - MIN_DECAY) * ((float)d / 767.0f));
        #pragma unroll
        for (int l = 0; l < 16; l++) {
            const int lg = l0 + l;
            const float t = (float)lg / 2047.0f;
            g_k[d*LL + lg] = acc[l] * expf(-t * delta);
        }
    }
}

// =====================================================================
// FFT helpers (512 threads per CTA)
// =====================================================================
__device__ __forceinline__ void copy_tw(float2* tw, int tid) {
    #pragma unroll
    for (int j = tid; j < NFFT/2; j += 512) tw[j] = g_tw[j];
}

__device__ void fft_dif_fwd(float2* data, const float2* tw, int tid) {
    #pragma unroll 1
    for (int s = 11; s >= 0; s--) {
        const int span = 1 << s;
        #pragma unroll
        for (int t = 0; t < 4; t++) {
            const int idx  = tid + t * 512;
            const int j    = idx & (span - 1);
            const int base = ((idx >> s) << (s + 1)) + j;
            const float2 a = data[base];
            const float2 b = data[base + span];
            data[base] = make_float2(a.x + b.x, a.y + b.y);
            const float2 d2 = make_float2(a.x - b.x, a.y - b.y);
            data[base + span] = cmul(d2, tw[j << (11 - s)]);
        }
        __syncthreads();
    }
}

__device__ void fft_dit_inv(float2* data, const float2* tw, int tid) {
    #pragma unroll 1
    for (int s = 0; s <= 11; s++) {
        const int span = 1 << s;
        #pragma unroll
        for (int t = 0; t < 4; t++) {
            const int idx  = tid + t * 512;
            const int j    = idx & (span - 1);
            const int base = ((idx >> s) << (s + 1)) + j;
            float2 w = tw[j << (11 - s)];
            w.y = -w.y;
            const float2 a = data[base];
            const float2 b = cmul(data[base + span], w);
            data[base]        = make_float2(a.x + b.x, a.y + b.y);
            data[base + span] = make_float2(a.x - b.x, a.y - b.y);
        }
        __syncthreads();
    }
}

// =====================================================================
// Kernel 2: FFT of filter k  ->  g_Kf
// =====================================================================
__global__ __launch_bounds__(512) void fftk_kernel() {
    __shared__ float2 data[NFFT];
    __shared__ float2 tw[NFFT/2];
    const int d = blockIdx.x;
    const int tid = threadIdx.x;
    copy_tw(tw, tid);
    #pragma unroll
    for (int i = tid; i < LL; i += 512) {
        data[i]      = make_float2(g_k[d*LL + i], 0.f);
        data[i + LL] = make_float2(0.f, 0.f);
    }
    __syncthreads();
    fft_dif_fwd(data, tw, tid);
    #pragma unroll
    for (int i = tid; i < NFFT; i += 512) g_Kf[(size_t)d*NFFT + i] = data[i];
}

// =====================================================================
// Prep: split fp32 -> bf16 hi/lo (same layout)
// =====================================================================
__global__ __launch_bounds__(256) void split_kernel(
    const float* __restrict__ in, __nv_bfloat16* __restrict__ oh,
    __nv_bfloat16* __restrict__ ol, int n4)
{
    const int i = blockIdx.x * 256 + threadIdx.x;
    if (i >= n4) return;
    const float4 v = reinterpret_cast<const float4*>(in)[i];
    __nv_bfloat16 h0 = __float2bfloat16(v.x), h1 = __float2bfloat16(v.y);
    __nv_bfloat16 h2 = __float2bfloat16(v.z), h3 = __float2bfloat16(v.w);
    __nv_bfloat16 l0 = __float2bfloat16(v.x - __bfloat162float(h0));
    __nv_bfloat16 l1 = __float2bfloat16(v.y - __bfloat162float(h1));
    __nv_bfloat16 l2 = __float2bfloat16(v.z - __bfloat162float(h2));
    __nv_bfloat16 l3 = __float2bfloat16(v.w - __bfloat162float(h3));
    reinterpret_cast<__nv_bfloat162*>(oh)[i*2]   = __nv_bfloat162(h0, h1);
    reinterpret_cast<__nv_bfloat162*>(oh)[i*2+1] = __nv_bfloat162(h2, h3);
    reinterpret_cast<__nv_bfloat162*>(ol)[i*2]   = __nv_bfloat162(l0, l1);
    reinterpret_cast<__nv_bfloat162*>(ol)[i*2+1] = __nv_bfloat162(l2, l3);
}

// =====================================================================
// Prep: transpose [R][C] fp32 -> [C][R] bf16 hi/lo (with batch)
// =====================================================================
__global__ __launch_bounds__(256) void transpose_split_kernel(
    const float* __restrict__ in, __nv_bfloat16* __restrict__ oh,
    __nv_bfloat16* __restrict__ ol, int R, int C,
    size_t inBatch, size_t outBatch)
{
    __shared__ float tile[32][33];
    const int b  = blockIdx.z;
    const float* src = in + (size_t)b * inBatch;
    const int r0 = blockIdx.y * 32, c0 = blockIdx.x * 32;
    const int tx = threadIdx.x & 31, ty = threadIdx.x >> 5;
    #pragma unroll
    for (int i = 0; i < 32; i += 8)
        tile[ty+i][tx] = src[(size_t)(r0+ty+i)*C + c0 + tx];
    __syncthreads();
    #pragma unroll
    for (int i = 0; i < 32; i += 8) {
        const float x = tile[tx][ty+i];
        const __nv_bfloat16 h = __float2bfloat16(x);
        const __nv_bfloat16 l = __float2bfloat16(x - __bfloat162float(h));
        const size_t o = (size_t)b*outBatch + (size_t)(c0+ty+i)*R + r0 + tx;
        oh[o] = h;
        ol[o] = l;
    }
}

// =====================================================================
// mma.sync GEMM: C[M][N] = A[M][K] @ B[N][K]^T + bias
// bf16 hi/lo 3-pass fp32 emulation; cp.async double-buffered pipeline.
// CTA tile 128x128, 8 warps (32m x 64n each), K-chunks of 16, 2 stages.
// =====================================================================
#define AS_STRIDE 24            // bf16 elems per smem row (16 data + 8 pad)
#define ARR_BYTES (128*AS_STRIDE*2)   // 6144 B per array

__global__ __launch_bounds__(256, 2) void gemm_mma_kernel(
    const __nv_bfloat16* __restrict__ Ah, const __nv_bfloat16* __restrict__ Al,
    const __nv_bfloat16* __restrict__ Bh, const __nv_bfloat16* __restrict__ Bl,
    const float* __restrict__ bias, float* __restrict__ C,
    int K, int N)
{
    // 2 stages x 4 arrays (AH, AL, BH, BL) x 6144 B = 49152 B
    __shared__ __align__(16) __nv_bfloat16 smbuf[2*4*128*AS_STRIDE];
    const uint32_t smem_base = smem_u32(smbuf);

    const int tid  = threadIdx.x;
    const int wid  = tid >> 5;
    const int lane = tid & 31;
    const int m0 = blockIdx.y * 128;
    const int n0 = blockIdx.x * 128;
    const int wm = (wid & 3) * 32;   // warp m offset in tile
    const int wn = (wid >> 2) * 64;  // warp n offset in tile

    // global/smem copy mapping: each thread one 16B segment per array
    const int lrow = tid >> 1;          // 0..127
    const int lsegB = (tid & 1) * 16;   // byte offset within row (0 or 16)
    const uint32_t cpdst = (uint32_t)lrow * (AS_STRIDE*2) + lsegB;

    // ldmatrix per-lane offsets (bytes, within one array)
    const int arow  = wm + (lane & 15);
    const uint32_t aoffs = (uint32_t)arow * (AS_STRIDE*2) + (uint32_t)(lane >> 4) * 16;
    const int brow  = wn + (lane & 7) + ((lane >> 4) & 1) * 8;
    const uint32_t boffs = (uint32_t)brow * (AS_STRIDE*2) + (uint32_t)((lane >> 3) & 1) * 16;

    float acc[2][8][4];
    #pragma unroll
    for (int i = 0; i < 2; i++)
        #pragma unroll
        for (int j = 0; j < 8; j++)
            #pragma unroll
            for (int q = 0; q < 4; q++) acc[i][j][q] = 0.f;

    const int NKB = K >> 4;   // 48

    // --- cp.async issue of one chunk into stage st ---
    #define ISSUE_CHUNK(k0, st) do {                                             \
        const size_t offA = (size_t)(m0 + lrow)*K + (k0);                        \
        const size_t offB = (size_t)(n0 + lrow)*K + (k0);                        \
        const uint32_t s0 = smem_base + (uint32_t)(st)*4*ARR_BYTES + cpdst;      \
        CP_ASYNC16(s0,               (const char*)(Ah + offA) + lsegB);          \
        CP_ASYNC16(s0 +   ARR_BYTES, (const char*)(Al + offA) + lsegB);          \
        CP_ASYNC16(s0 + 2*ARR_BYTES, (const char*)(Bh + offB) + lsegB);          \
        CP_ASYNC16(s0 + 3*ARR_BYTES, (const char*)(Bl + offB) + lsegB);          \
    } while (0)

    ISSUE_CHUNK(0, 0);
    CP_COMMIT();

    for (int kb = 0; kb < NKB; kb++) {
        const int st = kb & 1;
        if (kb + 1 < NKB) ISSUE_CHUNK((kb + 1) * 16, st ^ 1);
        CP_COMMIT();
        cp_wait<1>();
        __syncthreads();

        const uint32_t bAh = smem_base + (uint32_t)st*4*ARR_BYTES;
        const uint32_t bAl = bAh +   ARR_BYTES;
        const uint32_t bBh = bAh + 2*ARR_BYTES;
        const uint32_t bBl = bAh + 3*ARR_BYTES;

        uint32_t ah[2][4], al[2][4];
        ldmatrix_x4(ah[0][0], ah[0][1], ah[0][2], ah[0][3], bAh + aoffs);
        ldmatrix_x4(ah[1][0], ah[1][1], ah[1][2], ah[1][3], bAh + aoffs + 16*(AS_STRIDE*2));
        ldmatrix_x4(al[0][0], al[0][1], al[0][2], al[0][3], bAl + aoffs);
        ldmatrix_x4(al[1][0], al[1][1], al[1][2], al[1][3], bAl + aoffs + 16*(AS_STRIDE*2));

        #pragma unroll
        for (int p = 0; p < 4; p++) {
            uint32_t bh0, bh1, bh2, bh3, bl0, bl1, bl2, bl3;
            const uint32_t bo = boffs + (uint32_t)p * (16*AS_STRIDE*2);
            ldmatrix_x4(bh0, bh1, bh2, bh3, bBh + bo);
            ldmatrix_x4(bl0, bl1, bl2, bl3, bBl + bo);
            #pragma unroll
            for (int mt = 0; mt < 2; mt++) {
                mma16816(acc[mt][2*p],   ah[mt][0], ah[mt][1], ah[mt][2], ah[mt][3], bh0, bh1);
                mma16816(acc[mt][2*p],   ah[mt][0], ah[mt][1], ah[mt][2], ah[mt][3], bl0, bl1);
                mma16816(acc[mt][2*p],   al[mt][0], al[mt][1], al[mt][2], al[mt][3], bh0, bh1);
                mma16816(acc[mt][2*p+1], ah[mt][0], ah[mt][1], ah[mt][2], ah[mt][3], bh2, bh3);
                mma16816(acc[mt][2*p+1], ah[mt][0], ah[mt][1], ah[mt][2], ah[mt][3], bl2, bl3);
                mma16816(acc[mt][2*p+1], al[mt][0], al[mt][1], al[mt][2], al[mt][3], bh2, bh3);
            }
        }
        __syncthreads();
    }
    #undef ISSUE_CHUNK

    // epilogue: fragment layout -> gmem with bias
    const int crow = lane >> 2;
    const int ccol = (lane & 3) * 2;
    #pragma unroll
    for (int mt = 0; mt < 2; mt++) {
        const int mbase = m0 + wm + mt*16 + crow;
        #pragma unroll
        for (int nt = 0; nt < 8; nt++) {
            const int n = n0 + wn + nt*8 + ccol;
            const float b0 = bias[n], b1 = bias[n+1];
            float2 r0 = make_float2(acc[mt][nt][0] + b0, acc[mt][nt][1] + b1);
            float2 r1 = make_float2(acc[mt][nt][2] + b0, acc[mt][nt][3] + b1);
            *reinterpret_cast<float2*>(&C[(size_t)mbase*N + n])     = r0;
            *reinterpret_cast<float2*>(&C[(size_t)(mbase+8)*N + n]) = r1;
        }
    }
}

// =====================================================================
// depthwise conv-4 (causal) + gating + transpose
// =====================================================================
__global__ __launch_bounds__(256) void convgate_kernel(
    const float* __restrict__ x1_s, const float* __restrict__ x2_s,
    const float* __restrict__ v_s,
    const float* __restrict__ x1_sb, const float* __restrict__ x2_sb,
    const float* __restrict__ v_sb)
{
    __shared__ float sh1[35*33];
    __shared__ float sh2[35*33];
    __shared__ float shv[35*33];
    const int tid = threadIdx.x;
    const int d0 = blockIdx.x * 32;
    const int l0 = blockIdx.y * 32;
    const int b  = blockIdx.z;

    for (int idx = tid; idx < 35*32; idx += 256) {
        const int r  = idx >> 5;
        const int cc = idx & 31;
        const int lg = l0 - 3 + r;
        float v1 = 0.f, v2 = 0.f, vv = 0.f;
        if (lg >= 0) {
            const size_t rowbase = ((size_t)(b*LL + lg)) * N3D + d0 + cc;
            v1 = g_xbuf[rowbase];
            v2 = g_xbuf[rowbase + DD];
            vv = g_xbuf[rowbase + 2*DD];
        }
        sh1[r*33 + cc] = v1;
        sh2[r*33 + cc] = v2;
        shv[r*33 + cc] = vv;
    }
    __syncthreads();

    #pragma unroll
    for (int t = 0; t < 4; t++) {
        const int o  = tid + t*256;
        const int dd = o >> 5;
        const int ll = o & 31;
        const int d  = d0 + dd;
        float c1 = x1_sb[d], c2 = x2_sb[d], cv = v_sb[d];
        #pragma unroll
        for (int j = 0; j < 4; j++) {
            const int r = ll + j;
            c1 += x1_s[d*4 + j] * sh1[r*33 + dd];
            c2 += x2_s[d*4 + j] * sh2[r*33 + dd];
            cv += v_s [d*4 + j] * shv[r*33 + dd];
        }
        const size_t out = ((size_t)(b*DD + d)) * LL + l0 + ll;
        g_vg [out] = cv * c1;
        g_x2g[out] = c2;
    }
}

// =====================================================================
// per-channel FFT convolution + D_bias + x2 gate
// =====================================================================
__global__ __launch_bounds__(512) void fftconv_kernel(const float* __restrict__ D_bias) {
    __shared__ float2 data[NFFT];
    __shared__ float2 tw[NFFT/2];
    const int bd  = blockIdx.x;
    const int d   = bd % DD;
    const int tid = threadIdx.x;
    const size_t ch = (size_t)bd * LL;

    copy_tw(tw, tid);
    float vc[4];
    #pragma unroll
    for (int i = 0; i < 4; i++) {
        const int l = tid + i*512;
        const float v = g_vg[ch + l];
        vc[i] = v;
        data[l]      = make_float2(v, 0.f);
        data[l + LL] = make_float2(0.f, 0.f);
    }
    __syncthreads();

    fft_dif_fwd(data, tw, tid);

    const float2* __restrict__ kf = &g_Kf[(size_t)d * NFFT];
    #pragma unroll
    for (int i = tid; i < NFFT; i += 512) data[i] = cmul(data[i], kf[i]);
    __syncthreads();

    fft_dit_inv(data, tw, tid);

    const float db = D_bias[d];
    #pragma unroll
    for (int i = 0; i < 4; i++) {
        const int l = tid + i*512;
        const float yr = data[l].x * (1.0f / (float)NFFT);
        const float x2 = g_x2g[ch + l];
        g_ybT[ch + l] = (yr + vc[i] * db) * x2;
    }
}

// =====================================================================
// launch
// =====================================================================
extern "C" void kernel_launch(void* const* d_in, const int* in_sizes, int n_in,
                              void* d_out, int out_size) {
    const float* u      = (const float*)d_in[0];
    const float* in_W   = (const float*)d_in[1];
    const float* in_b   = (const float*)d_in[2];
    const float* out_W  = (const float*)d_in[3];
    const float* out_b  = (const float*)d_in[4];
    const float* x1_s   = (const float*)d_in[5];
    const float* x2_s   = (const float*)d_in[6];
    const float* v_s    = (const float*)d_in[7];
    const float* x1_sb  = (const float*)d_in[8];
    const float* x2_sb  = (const float*)d_in[9];
    const float* v_sb   = (const float*)d_in[10];
    const float* D_bias = (const float*)d_in[11];
    const float* z      = (const float*)d_in[12];
    const float* sfreq  = (const float*)d_in[13];
    const float* eo_mat = (const float*)d_in[14];
    const float* eo_b   = (const float*)d_in[15];
    const float* oo1    = (const float*)d_in[16];
    const float* oo1_b  = (const float*)d_in[17];
    const float* oo2    = (const float*)d_in[18];
    const float* oo2_b  = (const float*)d_in[19];
    const float* oh     = (const float*)d_in[20];
    float* out = (float*)d_out;

    float *xbuf, *ybT;
    __nv_bfloat16 *uh, *ul, *wh, *wl, *woh, *wol, *yh, *yl;
    cudaGetSymbolAddress((void**)&xbuf, g_xbuf);
    cudaGetSymbolAddress((void**)&ybT,  g_ybT);
    cudaGetSymbolAddress((void**)&uh,  g_uh);
    cudaGetSymbolAddress((void**)&ul,  g_ul);
    cudaGetSymbolAddress((void**)&wh,  g_wh);
    cudaGetSymbolAddress((void**)&wl,  g_wl);
    cudaGetSymbolAddress((void**)&woh, g_woh);
    cudaGetSymbolAddress((void**)&wol, g_wol);
    cudaGetSymbolAddress((void**)&yh,  g_yh);
    cudaGetSymbolAddress((void**)&yl,  g_yl);

    // filter + its FFT
    twinit_kernel<<<4, 512>>>();
    filter_kernel<<<LL/16, 128>>>(z, sfreq, eo_mat, eo_b, oo1, oo1_b, oo2, oo2_b, oh);
    fftk_kernel<<<DD, 512>>>();

    // bf16 split preps
    split_kernel<<<(MM*DD/4 + 255)/256, 256>>>(u, uh, ul, MM*DD/4);
    transpose_split_kernel<<<dim3(N3D/32, DD/32, 1), 256>>>(in_W,  wh,  wl,  DD, N3D, 0, 0);
    transpose_split_kernel<<<dim3(DD/32,  DD/32, 1), 256>>>(out_W, woh, wol, DD, DD,  0, 0);

    // GEMM1: [16384 x 768] @ [768 x 2304]
    gemm_mma_kernel<<<dim3(N3D/128, MM/128), 256>>>(uh, ul, wh, wl, in_b, xbuf, DD, N3D);

    convgate_kernel<<<dim3(DD/32, LL/32, BB), 256>>>(x1_s, x2_s, v_s, x1_sb, x2_sb, v_sb);
    fftconv_kernel<<<BB*DD, 512>>>(D_bias);

    // transpose gated output [b][d][l] -> [(b,l)][d] bf16 hi/lo
    transpose_split_kernel<<<dim3(LL/32, DD/32, BB), 256>>>(
        ybT, yh, yl, DD, LL, (size_t)DD*LL, (size_t)DD*LL);

    // GEMM2: [16384 x 768] @ [768 x 768]
    gemm_mma_kernel<<<dim3(DD/128, MM/128), 256>>>(yh, yl, woh, wol, out_b, out, DD, DD);
}

// round 7
// speedup vs baseline: 1.5987x; 1.0998x over previous
#include <cuda_runtime.h>
#include <cuda_bf16.h>
#include <cuda_fp16.h>
#include <math.h>
#include <stdint.h>

// Problem constants
#define BB   8
#define LL   2048
#define DD   768
#define ORD  128
#define NFFT 4096
#define MM   (BB*LL)          // 16384
#define N3D  (3*DD)           // 2304

#define MIN_DECAY (-3.0701134573253945f)
#define MAX_DECAY (-15.350567286626972f)

// ---------------- scratch (device globals; no allocations allowed) ------------
__device__ float  g_k[DD * LL];            // filter k[d][l]
__device__ float2 g_Kf[DD * NFFT];         // FFT(k) in DIF (bit-reversed) order
__device__ float2 g_tw[NFFT/2];            // twiddle table exp(-2*pi*i*j/4096)
__device__ float  g_xbuf[(size_t)MM * N3D];// u @ in_W + b   [m][c]
__device__ float  g_vg [BB * DD * LL];     // conv(v)*conv(x1), channel-major
__device__ float  g_x2g[BB * DD * LL];     // conv(x2), channel-major
__device__ float  g_ybT[BB * DD * LL];     // gated fftconv output, channel-major

// fp16 operands for tensor-core GEMMs (A single, B hi/lo split)
__device__ __half g_uh[(size_t)MM * DD];    // u as fp16        [m][k]
__device__ __half g_wh[(size_t)N3D * DD];   // in_W^T hi        [N][K]
__device__ __half g_wl[(size_t)N3D * DD];   // in_W^T lo
__device__ __half g_woh[(size_t)DD * DD];   // out_W^T hi       [N][K]
__device__ __half g_wol[(size_t)DD * DD];   // out_W^T lo
__device__ __half g_yh[(size_t)MM * DD];    // gated y as fp16  [m][k]

__device__ __forceinline__ float2 cmul(float2 a, float2 b) {
    return make_float2(a.x*b.x - a.y*b.y, a.x*b.y + a.y*b.x);
}

// ============================ mma helpers ====================================
__device__ __forceinline__ uint32_t smem_u32(const void* p) {
    uint32_t a;
    asm("{ .reg .u64 t; cvta.to.shared.u64 t, %1; cvt.u32.u64 %0, t; }" : "=r"(a) : "l"(p));
    return a;
}
__device__ __forceinline__ void ldmatrix_x4(uint32_t &r0, uint32_t &r1,
                                            uint32_t &r2, uint32_t &r3,
                                            uint32_t addr) {
    asm volatile("ldmatrix.sync.aligned.m8n8.x4.shared.b16 {%0,%1,%2,%3}, [%4];"
                 : "=r"(r0), "=r"(r1), "=r"(r2), "=r"(r3) : "r"(addr));
}
__device__ __forceinline__ void mma16816(float* c,
                                         uint32_t a0, uint32_t a1, uint32_t a2, uint32_t a3,
                                         uint32_t b0, uint32_t b1) {
    asm volatile("mma.sync.aligned.m16n8k16.row.col.f32.f16.f16.f32 "
                 "{%0,%1,%2,%3}, {%4,%5,%6,%7}, {%8,%9}, {%0,%1,%2,%3};"
                 : "+f"(c[0]), "+f"(c[1]), "+f"(c[2]), "+f"(c[3])
                 : "r"(a0), "r"(a1), "r"(a2), "r"(a3), "r"(b0), "r"(b1));
}
#define CP_ASYNC16(dst, src) \
    asm volatile("cp.async.cg.shared.global [%0], [%1], 16;" :: "r"(dst), "l"(src))
#define CP_COMMIT() asm volatile("cp.async.commit_group;" ::: "memory")
template<int N>
__device__ __forceinline__ void cp_wait() {
    asm volatile("cp.async.wait_group %0;" :: "n"(N) : "memory");
}

// =====================================================================
// twiddle table
// =====================================================================
__global__ __launch_bounds__(512) void twinit_kernel() {
    const int j = blockIdx.x * 512 + threadIdx.x;
    if (j < NFFT/2) {
        float s, c;
        sincospif(-(float)j / 2048.0f, &s, &c);
        g_tw[j] = make_float2(c, s);
    }
}

// =====================================================================
// Hyena filter  ->  g_k[d][l]
// =====================================================================
__global__ __launch_bounds__(128) void filter_kernel(
    const float* __restrict__ z, const float* __restrict__ sin_freq,
    const float* __restrict__ eo_mat, const float* __restrict__ eo_bias,
    const float* __restrict__ oo1, const float* __restrict__ oo1_b,
    const float* __restrict__ oo2, const float* __restrict__ oo2_b,
    const float* __restrict__ oh)
{
    __shared__ float hA[16][129];
    __shared__ float hB[16][129];
    const int o  = threadIdx.x;
    const int l0 = blockIdx.x * 16;
    const float f = sin_freq[o];

    #pragma unroll 1
    for (int l = 0; l < 16; l++) {
        float acc = eo_bias[o];
        #pragma unroll
        for (int e = 0; e < 5; e++) acc += z[(l0+l)*5 + e] * eo_mat[e*ORD + o];
        hA[l][o] = sinf(f * acc);
    }
    __syncthreads();
    #pragma unroll 1
    for (int l = 0; l < 16; l++) {
        float acc = oo1_b[o];
        #pragma unroll 4
        for (int p = 0; p < ORD; p++) acc += hA[l][p] * oo1[p*ORD + o];
        hB[l][o] = sinf(f * acc);
    }
    __syncthreads();
    #pragma unroll 1
    for (int l = 0; l < 16; l++) {
        float acc = oo2_b[o];
        #pragma unroll 4
        for (int p = 0; p < ORD; p++) acc += hB[l][p] * oo2[p*ORD + o];
        hA[l][o] = sinf(f * acc);
    }
    __syncthreads();
    #pragma unroll 1
    for (int c = 0; c < DD/ORD; c++) {
        const int d = o + c * ORD;
        float acc[16];
        #pragma unroll
        for (int l = 0; l < 16; l++) acc[l] = 0.f;
        #pragma unroll 2
        for (int p = 0; p < ORD; p++) {
            const float w = oh[p*DD + d];
            #pragma unroll
            for (int l = 0; l < 16; l++) acc[l] += hA[l][p] * w;
        }
        const float delta = fabsf(MIN_DECAY + (MAX_DECAY - MIN_DECAY) * ((float)d / 767.0f));
        #pragma unroll
        for (int l = 0; l < 16; l++) {
            const int lg = l0 + l;
            const float t = (float)lg / 2047.0f;
            g_k[d*LL + lg] = acc[l] * expf(-t * delta);
        }
    }
}

// =====================================================================
// FFT helpers (512 threads per CTA)
// =====================================================================
__device__ __forceinline__ void copy_tw(float2* tw, int tid) {
    #pragma unroll
    for (int j = tid; j < NFFT/2; j += 512) tw[j] = g_tw[j];
}

__device__ void fft_dif_fwd(float2* data, const float2* tw, int tid) {
    #pragma unroll 1
    for (int s = 11; s >= 0; s--) {
        const int span = 1 << s;
        #pragma unroll
        for (int t = 0; t < 4; t++) {
            const int idx  = tid + t * 512;
            const int j    = idx & (span - 1);
            const int base = ((idx >> s) << (s + 1)) + j;
            const float2 a = data[base];
            const float2 b = data[base + span];
            data[base] = make_float2(a.x + b.x, a.y + b.y);
            const float2 d2 = make_float2(a.x - b.x, a.y - b.y);
            data[base + span] = cmul(d2, tw[j << (11 - s)]);
        }
        __syncthreads();
    }
}

__device__ void fft_dit_inv(float2* data, const float2* tw, int tid) {
    #pragma unroll 1
    for (int s = 0; s <= 11; s++) {
        const int span = 1 << s;
        #pragma unroll
        for (int t = 0; t < 4; t++) {
            const int idx  = tid + t * 512;
            const int j    = idx & (span - 1);
            const int base = ((idx >> s) << (s + 1)) + j;
            float2 w = tw[j << (11 - s)];
            w.y = -w.y;
            const float2 a = data[base];
            const float2 b = cmul(data[base + span], w);
            data[base]        = make_float2(a.x + b.x, a.y + b.y);
            data[base + span] = make_float2(a.x - b.x, a.y - b.y);
        }
        __syncthreads();
    }
}

// =====================================================================
// FFT of filter k  ->  g_Kf
// =====================================================================
__global__ __launch_bounds__(512) void fftk_kernel() {
    __shared__ float2 data[NFFT];
    __shared__ float2 tw[NFFT/2];
    const int d = blockIdx.x;
    const int tid = threadIdx.x;
    copy_tw(tw, tid);
    #pragma unroll
    for (int i = tid; i < LL; i += 512) {
        data[i]      = make_float2(g_k[d*LL + i], 0.f);
        data[i + LL] = make_float2(0.f, 0.f);
    }
    __syncthreads();
    fft_dif_fwd(data, tw, tid);
    #pragma unroll
    for (int i = tid; i < NFFT; i += 512) g_Kf[(size_t)d*NFFT + i] = data[i];
}

// =====================================================================
// Prep: convert fp32 -> fp16 (same layout)
// =====================================================================
__global__ __launch_bounds__(256) void convert_kernel(
    const float* __restrict__ in, __half* __restrict__ out, int n4)
{
    const int i = blockIdx.x * 256 + threadIdx.x;
    if (i >= n4) return;
    const float4 v = reinterpret_cast<const float4*>(in)[i];
    reinterpret_cast<__half2*>(out)[i*2]   = __floats2half2_rn(v.x, v.y);
    reinterpret_cast<__half2*>(out)[i*2+1] = __floats2half2_rn(v.z, v.w);
}

// =====================================================================
// Prep: transpose [R][C] fp32 -> [C][R] fp16 hi/lo (weights)
// =====================================================================
__global__ __launch_bounds__(256) void transpose_split_kernel(
    const float* __restrict__ in, __half* __restrict__ oh,
    __half* __restrict__ ol, int R, int C)
{
    __shared__ float tile[32][33];
    const int r0 = blockIdx.y * 32, c0 = blockIdx.x * 32;
    const int tx = threadIdx.x & 31, ty = threadIdx.x >> 5;
    #pragma unroll
    for (int i = 0; i < 32; i += 8)
        tile[ty+i][tx] = in[(size_t)(r0+ty+i)*C + c0 + tx];
    __syncthreads();
    #pragma unroll
    for (int i = 0; i < 32; i += 8) {
        const float x = tile[tx][ty+i];
        const __half h = __float2half_rn(x);
        const __half l = __float2half_rn(x - __half2float(h));
        const size_t o = (size_t)(c0+ty+i)*R + r0 + tx;
        oh[o] = h;
        ol[o] = l;
    }
}

// =====================================================================
// Prep: transpose [b][R][C] fp32 -> [b][C][R] fp16 (activation y)
// =====================================================================
__global__ __launch_bounds__(256) void transpose_convert_kernel(
    const float* __restrict__ in, __half* __restrict__ out, int R, int C,
    size_t batchStride)
{
    __shared__ float tile[32][33];
    const int b  = blockIdx.z;
    const float* src = in + (size_t)b * batchStride;
    const int r0 = blockIdx.y * 32, c0 = blockIdx.x * 32;
    const int tx = threadIdx.x & 31, ty = threadIdx.x >> 5;
    #pragma unroll
    for (int i = 0; i < 32; i += 8)
        tile[ty+i][tx] = src[(size_t)(r0+ty+i)*C + c0 + tx];
    __syncthreads();
    #pragma unroll
    for (int i = 0; i < 32; i += 8) {
        const size_t o = (size_t)b*batchStride + (size_t)(c0+ty+i)*R + r0 + tx;
        out[o] = __float2half_rn(tile[tx][ty+i]);
    }
}

// =====================================================================
// mma.sync GEMM: C[M][N] = A[M][K] @ (Bh+Bl)[N][K]^T + bias
// A fp16; B fp16 hi/lo -> 2 mma passes. cp.async 2-stage pipeline.
// CTA tile 128x128, 8 warps (32m x 64n each), K-chunks of 16.
// =====================================================================
#define AS_STRIDE 24                  // halves per smem row (16 data + 8 pad)
#define ARR_BYTES (128*AS_STRIDE*2)   // 6144 B per array

__global__ __launch_bounds__(256, 2) void gemm_mma_kernel(
    const __half* __restrict__ A,
    const __half* __restrict__ Bh, const __half* __restrict__ Bl,
    const float* __restrict__ bias, float* __restrict__ C,
    int K, int N)
{
    // 2 stages x 3 arrays (A, BH, BL) x 6144 B = 36864 B
    __shared__ __align__(16) __half smbuf[2*3*128*AS_STRIDE];
    const uint32_t smem_base = smem_u32(smbuf);

    const int tid  = threadIdx.x;
    const int wid  = tid >> 5;
    const int lane = tid & 31;
    const int m0 = blockIdx.y * 128;
    const int n0 = blockIdx.x * 128;
    const int wm = (wid & 3) * 32;   // warp m offset in tile
    const int wn = (wid >> 2) * 64;  // warp n offset in tile

    // global/smem copy mapping: each thread one 16B segment per array
    const int lrow = tid >> 1;          // 0..127
    const int lsegB = (tid & 1) * 16;   // byte offset within row (0 or 16)
    const uint32_t cpdst = (uint32_t)lrow * (AS_STRIDE*2) + lsegB;

    // ldmatrix per-lane offsets (bytes, within one array)
    const int arow  = wm + (lane & 15);
    const uint32_t aoffs = (uint32_t)arow * (AS_STRIDE*2) + (uint32_t)(lane >> 4) * 16;
    const int brow  = wn + (lane & 7) + ((lane >> 4) & 1) * 8;
    const uint32_t boffs = (uint32_t)brow * (AS_STRIDE*2) + (uint32_t)((lane >> 3) & 1) * 16;

    float acc[2][8][4];
    #pragma unroll
    for (int i = 0; i < 2; i++)
        #pragma unroll
        for (int j = 0; j < 8; j++)
            #pragma unroll
            for (int q = 0; q < 4; q++) acc[i][j][q] = 0.f;

    const int NKB = K >> 4;   // 48

    #define ISSUE_CHUNK(k0, st) do {                                             \
        const size_t offA = (size_t)(m0 + lrow)*K + (k0);                        \
        const size_t offB = (size_t)(n0 + lrow)*K + (k0);                        \
        const uint32_t s0 = smem_base + (uint32_t)(st)*3*ARR_BYTES + cpdst;      \
        CP_ASYNC16(s0,               (const char*)(A  + offA) + lsegB);          \
        CP_ASYNC16(s0 +   ARR_BYTES, (const char*)(Bh + offB) + lsegB);          \
        CP_ASYNC16(s0 + 2*ARR_BYTES, (const char*)(Bl + offB) + lsegB);          \
    } while (0)

    ISSUE_CHUNK(0, 0);
    CP_COMMIT();

    for (int kb = 0; kb < NKB; kb++) {
        const int st = kb & 1;
        if (kb + 1 < NKB) ISSUE_CHUNK((kb + 1) * 16, st ^ 1);
        CP_COMMIT();
        cp_wait<1>();
        __syncthreads();

        const uint32_t bA  = smem_base + (uint32_t)st*3*ARR_BYTES;
        const uint32_t bBh = bA +   ARR_BYTES;
        const uint32_t bBl = bA + 2*ARR_BYTES;

        uint32_t ah[2][4];
        ldmatrix_x4(ah[0][0], ah[0][1], ah[0][2], ah[0][3], bA + aoffs);
        ldmatrix_x4(ah[1][0], ah[1][1], ah[1][2], ah[1][3], bA + aoffs + 16*(AS_STRIDE*2));

        #pragma unroll
        for (int p = 0; p < 4; p++) {
            uint32_t bh0, bh1, bh2, bh3, bl0, bl1, bl2, bl3;
            const uint32_t bo = boffs + (uint32_t)p * (16*AS_STRIDE*2);
            ldmatrix_x4(bh0, bh1, bh2, bh3, bBh + bo);
            ldmatrix_x4(bl0, bl1, bl2, bl3, bBl + bo);
            #pragma unroll
            for (int mt = 0; mt < 2; mt++) {
                mma16816(acc[mt][2*p],   ah[mt][0], ah[mt][1], ah[mt][2], ah[mt][3], bh0, bh1);
                mma16816(acc[mt][2*p],   ah[mt][0], ah[mt][1], ah[mt][2], ah[mt][3], bl0, bl1);
                mma16816(acc[mt][2*p+1], ah[mt][0], ah[mt][1], ah[mt][2], ah[mt][3], bh2, bh3);
                mma16816(acc[mt][2*p+1], ah[mt][0], ah[mt][1], ah[mt][2], ah[mt][3], bl2, bl3);
            }
        }
        __syncthreads();
    }
    #undef ISSUE_CHUNK

    // epilogue: fragment layout -> gmem with bias
    const int crow = lane >> 2;
    const int ccol = (lane & 3) * 2;
    #pragma unroll
    for (int mt = 0; mt < 2; mt++) {
        const int mbase = m0 + wm + mt*16 + crow;
        #pragma unroll
        for (int nt = 0; nt < 8; nt++) {
            const int n = n0 + wn + nt*8 + ccol;
            const float b0 = bias[n], b1 = bias[n+1];
            float2 r0 = make_float2(acc[mt][nt][0] + b0, acc[mt][nt][1] + b1);
            float2 r1 = make_float2(acc[mt][nt][2] + b0, acc[mt][nt][3] + b1);
            *reinterpret_cast<float2*>(&C[(size_t)mbase*N + n])     = r0;
            *reinterpret_cast<float2*>(&C[(size_t)(mbase+8)*N + n]) = r1;
        }
    }
}

// =====================================================================
// depthwise conv-4 (causal) + gating + transpose
// =====================================================================
__global__ __launch_bounds__(256) void convgate_kernel(
    const float* __restrict__ x1_s, const float* __restrict__ x2_s,
    const float* __restrict__ v_s,
    const float* __restrict__ x1_sb, const float* __restrict__ x2_sb,
    const float* __restrict__ v_sb)
{
    __shared__ float sh1[35*33];
    __shared__ float sh2[35*33];
    __shared__ float shv[35*33];
    const int tid = threadIdx.x;
    const int d0 = blockIdx.x * 32;
    const int l0 = blockIdx.y * 32;
    const int b  = blockIdx.z;

    for (int idx = tid; idx < 35*32; idx += 256) {
        const int r  = idx >> 5;
        const int cc = idx & 31;
        const int lg = l0 - 3 + r;
        float v1 = 0.f, v2 = 0.f, vv = 0.f;
        if (lg >= 0) {
            const size_t rowbase = ((size_t)(b*LL + lg)) * N3D + d0 + cc;
            v1 = g_xbuf[rowbase];
            v2 = g_xbuf[rowbase + DD];
            vv = g_xbuf[rowbase + 2*DD];
        }
        sh1[r*33 + cc] = v1;
        sh2[r*33 + cc] = v2;
        shv[r*33 + cc] = vv;
    }
    __syncthreads();

    #pragma unroll
    for (int t = 0; t < 4; t++) {
        const int o  = tid + t*256;
        const int dd = o >> 5;
        const int ll = o & 31;
        const int d  = d0 + dd;
        float c1 = x1_sb[d], c2 = x2_sb[d], cv = v_sb[d];
        #pragma unroll
        for (int j = 0; j < 4; j++) {
            const int r = ll + j;
            c1 += x1_s[d*4 + j] * sh1[r*33 + dd];
            c2 += x2_s[d*4 + j] * sh2[r*33 + dd];
            cv += v_s [d*4 + j] * shv[r*33 + dd];
        }
        const size_t out = ((size_t)(b*DD + d)) * LL + l0 + ll;
        g_vg [out] = cv * c1;
        g_x2g[out] = c2;
    }
}

// =====================================================================
// per-channel FFT convolution + D_bias + x2 gate
// =====================================================================
__global__ __launch_bounds__(512) void fftconv_kernel(const float* __restrict__ D_bias) {
    __shared__ float2 data[NFFT];
    __shared__ float2 tw[NFFT/2];
    const int bd  = blockIdx.x;
    const int d   = bd % DD;
    const int tid = threadIdx.x;
    const size_t ch = (size_t)bd * LL;

    copy_tw(tw, tid);
    float vc[4];
    #pragma unroll
    for (int i = 0; i < 4; i++) {
        const int l = tid + i*512;
        const float v = g_vg[ch + l];
        vc[i] = v;
        data[l]      = make_float2(v, 0.f);
        data[l + LL] = make_float2(0.f, 0.f);
    }
    __syncthreads();

    fft_dif_fwd(data, tw, tid);

    const float2* __restrict__ kf = &g_Kf[(size_t)d * NFFT];
    #pragma unroll
    for (int i = tid; i < NFFT; i += 512) data[i] = cmul(data[i], kf[i]);
    __syncthreads();

    fft_dit_inv(data, tw, tid);

    const float db = D_bias[d];
    #pragma unroll
    for (int i = 0; i < 4; i++) {
        const int l = tid + i*512;
        const float yr = data[l].x * (1.0f / (float)NFFT);
        const float x2 = g_x2g[ch + l];
        g_ybT[ch + l] = (yr + vc[i] * db) * x2;
    }
}

// =====================================================================
// launch  (gemm1 is deliberately the 4th launch: ncu captures launch #4)
// =====================================================================
extern "C" void kernel_launch(void* const* d_in, const int* in_sizes, int n_in,
                              void* d_out, int out_size) {
    const float* u      = (const float*)d_in[0];
    const float* in_W   = (const float*)d_in[1];
    const float* in_b   = (const float*)d_in[2];
    const float* out_W  = (const float*)d_in[3];
    const float* out_b  = (const float*)d_in[4];
    const float* x1_s   = (const float*)d_in[5];
    const float* x2_s   = (const float*)d_in[6];
    const float* v_s    = (const float*)d_in[7];
    const float* x1_sb  = (const float*)d_in[8];
    const float* x2_sb  = (const float*)d_in[9];
    const float* v_sb   = (const float*)d_in[10];
    const float* D_bias = (const float*)d_in[11];
    const float* z      = (const float*)d_in[12];
    const float* sfreq  = (const float*)d_in[13];
    const float* eo_mat = (const float*)d_in[14];
    const float* eo_b   = (const float*)d_in[15];
    const float* oo1    = (const float*)d_in[16];
    const float* oo1_b  = (const float*)d_in[17];
    const float* oo2    = (const float*)d_in[18];
    const float* oo2_b  = (const float*)d_in[19];
    const float* oh     = (const float*)d_in[20];
    float* out = (float*)d_out;

    float *xbuf, *ybT;
    __half *uh, *wh, *wl, *woh, *wol, *yh;
    cudaGetSymbolAddress((void**)&xbuf, g_xbuf);
    cudaGetSymbolAddress((void**)&ybT,  g_ybT);
    cudaGetSymbolAddress((void**)&uh,  g_uh);
    cudaGetSymbolAddress((void**)&wh,  g_wh);
    cudaGetSymbolAddress((void**)&wl,  g_wl);
    cudaGetSymbolAddress((void**)&woh, g_woh);
    cudaGetSymbolAddress((void**)&wol, g_wol);
    cudaGetSymbolAddress((void**)&yh,  g_yh);

    // (1-3) GEMM1 operand preps
    convert_kernel<<<(MM*DD/4 + 255)/256, 256>>>(u, uh, MM*DD/4);
    transpose_split_kernel<<<dim3(N3D/32, DD/32), 256>>>(in_W,  wh,  wl,  DD, N3D);
    transpose_split_kernel<<<dim3(DD/32,  DD/32), 256>>>(out_W, woh, wol, DD, DD);

    // (4) GEMM1: [16384 x 768] @ [768 x 2304]  <- ncu-captured launch
    gemm_mma_kernel<<<dim3(N3D/128, MM/128), 256>>>(uh, wh, wl, in_b, xbuf, DD, N3D);

    // (5-7) filter chain (independent of GEMM1)
    twinit_kernel<<<4, 512>>>();
    filter_kernel<<<LL/16, 128>>>(z, sfreq, eo_mat, eo_b, oo1, oo1_b, oo2, oo2_b, oh);
    fftk_kernel<<<DD, 512>>>();

    // (8-9) conv/gate + FFT convolution
    convgate_kernel<<<dim3(DD/32, LL/32, BB), 256>>>(x1_s, x2_s, v_s, x1_sb, x2_sb, v_sb);
    fftconv_kernel<<<BB*DD, 512>>>(D_bias);

    // (10) y -> [(b,l)][d] fp16
    transpose_convert_kernel<<<dim3(LL/32, DD/32, BB), 256>>>(
        ybT, yh, DD, LL, (size_t)DD*LL);

    // (11) GEMM2: [16384 x 768] @ [768 x 768]
    gemm_mma_kernel<<<dim3(DD/128, MM/128), 256>>>(yh, woh, wol, out_b, out, DD, DD);
}

// round 8
// speedup vs baseline: 2.1133x; 1.3219x over previous
#include <cuda_runtime.h>
#include <cuda_bf16.h>
#include <cuda_fp16.h>
#include <math.h>
#include <stdint.h>

// Problem constants
#define BB   8
#define LL   2048
#define DD   768
#define ORD  128
#define NFFT 4096
#define MM   (BB*LL)          // 16384
#define N3D  (3*DD)           // 2304

#define MIN_DECAY (-3.0701134573253945f)
#define MAX_DECAY (-15.350567286626972f)

// ---------------- scratch (device globals; no allocations allowed) ------------
__device__ float  g_k[DD * LL];            // filter k[d][l]
__device__ float2 g_Kf[DD * NFFT];         // FFT(k) in DIF (bit-reversed) order
__device__ float2 g_tw[NFFT/2];            // twiddle table exp(-2*pi*i*j/4096)
__device__ float  g_xbuf[(size_t)MM * N3D];// u @ in_W + b   [m][c]
__device__ float  g_vg [BB * DD * LL];     // conv(v)*conv(x1), channel-major
__device__ float  g_x2g[BB * DD * LL];     // conv(x2), channel-major
__device__ float  g_ybT[BB * DD * LL];     // gated fftconv output, channel-major

// fp16 operands for tensor-core GEMMs (A single, B hi/lo split)
__device__ __half g_uh[(size_t)MM * DD];    // u as fp16        [m][k]
__device__ __half g_wh[(size_t)N3D * DD];   // in_W^T hi        [N][K]
__device__ __half g_wl[(size_t)N3D * DD];   // in_W^T lo
__device__ __half g_woh[(size_t)DD * DD];   // out_W^T hi       [N][K]
__device__ __half g_wol[(size_t)DD * DD];   // out_W^T lo
__device__ __half g_yh[(size_t)MM * DD];    // gated y as fp16  [m][k]

__device__ __forceinline__ float2 cmul(float2 a, float2 b) {
    return make_float2(a.x*b.x - a.y*b.y, a.x*b.y + a.y*b.x);
}

// ============================ mma helpers ====================================
__device__ __forceinline__ uint32_t smem_u32(const void* p) {
    uint32_t a;
    asm("{ .reg .u64 t; cvta.to.shared.u64 t, %1; cvt.u32.u64 %0, t; }" : "=r"(a) : "l"(p));
    return a;
}
__device__ __forceinline__ void ldmatrix_x4(uint32_t &r0, uint32_t &r1,
                                            uint32_t &r2, uint32_t &r3,
                                            uint32_t addr) {
    asm volatile("ldmatrix.sync.aligned.m8n8.x4.shared.b16 {%0,%1,%2,%3}, [%4];"
                 : "=r"(r0), "=r"(r1), "=r"(r2), "=r"(r3) : "r"(addr));
}
__device__ __forceinline__ void mma16816(float* c,
                                         uint32_t a0, uint32_t a1, uint32_t a2, uint32_t a3,
                                         uint32_t b0, uint32_t b1) {
    asm volatile("mma.sync.aligned.m16n8k16.row.col.f32.f16.f16.f32 "
                 "{%0,%1,%2,%3}, {%4,%5,%6,%7}, {%8,%9}, {%0,%1,%2,%3};"
                 : "+f"(c[0]), "+f"(c[1]), "+f"(c[2]), "+f"(c[3])
                 : "r"(a0), "r"(a1), "r"(a2), "r"(a3), "r"(b0), "r"(b1));
}
#define CP_ASYNC16(dst, src) \
    asm volatile("cp.async.cg.shared.global [%0], [%1], 16;" :: "r"(dst), "l"(src))
#define CP_COMMIT() asm volatile("cp.async.commit_group;" ::: "memory")
template<int N>
__device__ __forceinline__ void cp_wait() {
    asm volatile("cp.async.wait_group %0;" :: "n"(N) : "memory");
}

// =====================================================================
// twiddle table
// =====================================================================
__global__ __launch_bounds__(512) void twinit_kernel() {
    const int j = blockIdx.x * 512 + threadIdx.x;
    if (j < NFFT/2) {
        float s, c;
        sincospif(-(float)j / 2048.0f, &s, &c);
        g_tw[j] = make_float2(c, s);
    }
}

// =====================================================================
// Hyena filter  ->  g_k[d][l]
// =====================================================================
__global__ __launch_bounds__(128) void filter_kernel(
    const float* __restrict__ z, const float* __restrict__ sin_freq,
    const float* __restrict__ eo_mat, const float* __restrict__ eo_bias,
    const float* __restrict__ oo1, const float* __restrict__ oo1_b,
    const float* __restrict__ oo2, const float* __restrict__ oo2_b,
    const float* __restrict__ oh)
{
    __shared__ float hA[16][129];
    __shared__ float hB[16][129];
    const int o  = threadIdx.x;
    const int l0 = blockIdx.x * 16;
    const float f = sin_freq[o];

    #pragma unroll 1
    for (int l = 0; l < 16; l++) {
        float acc = eo_bias[o];
        #pragma unroll
        for (int e = 0; e < 5; e++) acc += z[(l0+l)*5 + e] * eo_mat[e*ORD + o];
        hA[l][o] = sinf(f * acc);
    }
    __syncthreads();
    #pragma unroll 1
    for (int l = 0; l < 16; l++) {
        float acc = oo1_b[o];
        #pragma unroll 4
        for (int p = 0; p < ORD; p++) acc += hA[l][p] * oo1[p*ORD + o];
        hB[l][o] = sinf(f * acc);
    }
    __syncthreads();
    #pragma unroll 1
    for (int l = 0; l < 16; l++) {
        float acc = oo2_b[o];
        #pragma unroll 4
        for (int p = 0; p < ORD; p++) acc += hB[l][p] * oo2[p*ORD + o];
        hA[l][o] = sinf(f * acc);
    }
    __syncthreads();
    #pragma unroll 1
    for (int c = 0; c < DD/ORD; c++) {
        const int d = o + c * ORD;
        float acc[16];
        #pragma unroll
        for (int l = 0; l < 16; l++) acc[l] = 0.f;
        #pragma unroll 2
        for (int p = 0; p < ORD; p++) {
            const float w = oh[p*DD + d];
            #pragma unroll
            for (int l = 0; l < 16; l++) acc[l] += hA[l][p] * w;
        }
        const float delta = fabsf(MIN_DECAY + (MAX_DECAY - MIN_DECAY) * ((float)d / 767.0f));
        #pragma unroll
        for (int l = 0; l < 16; l++) {
            const int lg = l0 + l;
            const float t = (float)lg / 2047.0f;
            g_k[d*LL + lg] = acc[l] * expf(-t * delta);
        }
    }
}

// =====================================================================
// FFT helpers (512 threads per CTA)
// =====================================================================
__device__ __forceinline__ void copy_tw(float2* tw, int tid) {
    #pragma unroll
    for (int j = tid; j < NFFT/2; j += 512) tw[j] = g_tw[j];
}

__device__ void fft_dif_fwd(float2* data, const float2* tw, int tid) {
    #pragma unroll 1
    for (int s = 11; s >= 0; s--) {
        const int span = 1 << s;
        #pragma unroll
        for (int t = 0; t < 4; t++) {
            const int idx  = tid + t * 512;
            const int j    = idx & (span - 1);
            const int base = ((idx >> s) << (s + 1)) + j;
            const float2 a = data[base];
            const float2 b = data[base + span];
            data[base] = make_float2(a.x + b.x, a.y + b.y);
            const float2 d2 = make_float2(a.x - b.x, a.y - b.y);
            data[base + span] = cmul(d2, tw[j << (11 - s)]);
        }
        __syncthreads();
    }
}

__device__ void fft_dit_inv(float2* data, const float2* tw, int tid) {
    #pragma unroll 1
    for (int s = 0; s <= 11; s++) {
        const int span = 1 << s;
        #pragma unroll
        for (int t = 0; t < 4; t++) {
            const int idx  = tid + t * 512;
            const int j    = idx & (span - 1);
            const int base = ((idx >> s) << (s + 1)) + j;
            float2 w = tw[j << (11 - s)];
            w.y = -w.y;
            const float2 a = data[base];
            const float2 b = cmul(data[base + span], w);
            data[base]        = make_float2(a.x + b.x, a.y + b.y);
            data[base + span] = make_float2(a.x - b.x, a.y - b.y);
        }
        __syncthreads();
    }
}

// =====================================================================
// FFT of filter k  ->  g_Kf
// =====================================================================
__global__ __launch_bounds__(512) void fftk_kernel() {
    __shared__ float2 data[NFFT];
    __shared__ float2 tw[NFFT/2];
    const int d = blockIdx.x;
    const int tid = threadIdx.x;
    copy_tw(tw, tid);
    #pragma unroll
    for (int i = tid; i < LL; i += 512) {
        data[i]      = make_float2(g_k[d*LL + i], 0.f);
        data[i + LL] = make_float2(0.f, 0.f);
    }
    __syncthreads();
    fft_dif_fwd(data, tw, tid);
    #pragma unroll
    for (int i = tid; i < NFFT; i += 512) g_Kf[(size_t)d*NFFT + i] = data[i];
}

// =====================================================================
// Prep: convert fp32 -> fp16 (same layout)
// =====================================================================
__global__ __launch_bounds__(256) void convert_kernel(
    const float* __restrict__ in, __half* __restrict__ out, int n4)
{
    const int i = blockIdx.x * 256 + threadIdx.x;
    if (i >= n4) return;
    const float4 v = reinterpret_cast<const float4*>(in)[i];
    reinterpret_cast<__half2*>(out)[i*2]   = __floats2half2_rn(v.x, v.y);
    reinterpret_cast<__half2*>(out)[i*2+1] = __floats2half2_rn(v.z, v.w);
}

// =====================================================================
// Prep: transpose [R][C] fp32 -> [C][R] fp16 hi/lo (weights)
// =====================================================================
__global__ __launch_bounds__(256) void transpose_split_kernel(
    const float* __restrict__ in, __half* __restrict__ oh,
    __half* __restrict__ ol, int R, int C)
{
    __shared__ float tile[32][33];
    const int r0 = blockIdx.y * 32, c0 = blockIdx.x * 32;
    const int tx = threadIdx.x & 31, ty = threadIdx.x >> 5;
    #pragma unroll
    for (int i = 0; i < 32; i += 8)
        tile[ty+i][tx] = in[(size_t)(r0+ty+i)*C + c0 + tx];
    __syncthreads();
    #pragma unroll
    for (int i = 0; i < 32; i += 8) {
        const float x = tile[tx][ty+i];
        const __half h = __float2half_rn(x);
        const __half l = __float2half_rn(x - __half2float(h));
        const size_t o = (size_t)(c0+ty+i)*R + r0 + tx;
        oh[o] = h;
        ol[o] = l;
    }
}

// =====================================================================
// Prep: transpose [b][R][C] fp32 -> [b][C][R] fp16 (activation y)
// =====================================================================
__global__ __launch_bounds__(256) void transpose_convert_kernel(
    const float* __restrict__ in, __half* __restrict__ out, int R, int C,
    size_t batchStride)
{
    __shared__ float tile[32][33];
    const int b  = blockIdx.z;
    const float* src = in + (size_t)b * batchStride;
    const int r0 = blockIdx.y * 32, c0 = blockIdx.x * 32;
    const int tx = threadIdx.x & 31, ty = threadIdx.x >> 5;
    #pragma unroll
    for (int i = 0; i < 32; i += 8)
        tile[ty+i][tx] = src[(size_t)(r0+ty+i)*C + c0 + tx];
    __syncthreads();
    #pragma unroll
    for (int i = 0; i < 32; i += 8) {
        const size_t o = (size_t)b*batchStride + (size_t)(c0+ty+i)*R + r0 + tx;
        out[o] = __float2half_rn(tile[tx][ty+i]);
    }
}

// =====================================================================
// mma.sync GEMM: C[M][N] = A[M][K] @ (Bh+Bl)[N][K]^T + bias
// A fp16; B fp16 hi/lo -> 2 mma passes. cp.async 2-stage pipeline.
// CTA tile 128x128, 8 warps (32m x 64n each), K-chunks of 32.
// =====================================================================
#define KB       32                   // K halves per chunk
#define AS_STRIDE 40                  // halves per smem row (32 data + 8 pad)
#define ARR_BYTES (128*AS_STRIDE*2)   // 10240 B per array

__global__ __launch_bounds__(256, 2) void gemm_mma_kernel(
    const __half* __restrict__ A,
    const __half* __restrict__ Bh, const __half* __restrict__ Bl,
    const float* __restrict__ bias, float* __restrict__ C,
    int K, int N)
{
    // 2 stages x 3 arrays (A, BH, BL) x 10240 B = 61440 B
    __shared__ __align__(16) __half smbuf[2*3*128*AS_STRIDE];
    const uint32_t smem_base = smem_u32(smbuf);

    const int tid  = threadIdx.x;
    const int wid  = tid >> 5;
    const int lane = tid & 31;
    const int m0 = blockIdx.y * 128;
    const int n0 = blockIdx.x * 128;
    const int wm = (wid & 3) * 32;   // warp m offset in tile
    const int wn = (wid >> 2) * 64;  // warp n offset in tile

    // copy mapping: 512 16B-segments per array, 2 per thread
    // seg = tid + t*256; row = seg>>2 (0..127); part = seg&3 (k-quarter)
    const int r0s = tid >> 2;
    const int p0s = tid & 3;

    // ldmatrix per-lane offsets (bytes, within one array)
    const int arow  = wm + (lane & 15);
    const uint32_t aoffs = (uint32_t)arow * (AS_STRIDE*2) + (uint32_t)(lane >> 4) * 16;
    const int brow  = wn + (lane & 7) + ((lane >> 4) & 1) * 8;
    const uint32_t boffs = (uint32_t)brow * (AS_STRIDE*2) + (uint32_t)((lane >> 3) & 1) * 16;

    float acc[2][8][4];
    #pragma unroll
    for (int i = 0; i < 2; i++)
        #pragma unroll
        for (int j = 0; j < 8; j++)
            #pragma unroll
            for (int q = 0; q < 4; q++) acc[i][j][q] = 0.f;

    const int NKB = K / KB;   // 24

    #define ISSUE_CHUNK(k0, st) do {                                                 \
        const uint32_t sbase = smem_base + (uint32_t)(st)*3*ARR_BYTES;               \
        _Pragma("unroll")                                                            \
        for (int t = 0; t < 2; t++) {                                                \
            const int row  = r0s + t*64;                                             \
            const int kk   = (k0) + p0s*8;                                           \
            const uint32_t dst = sbase + (uint32_t)row*(AS_STRIDE*2) + p0s*16;       \
            CP_ASYNC16(dst,               (const char*)(A  + (size_t)(m0+row)*K + kk)); \
            CP_ASYNC16(dst +   ARR_BYTES, (const char*)(Bh + (size_t)(n0+row)*K + kk)); \
            CP_ASYNC16(dst + 2*ARR_BYTES, (const char*)(Bl + (size_t)(n0+row)*K + kk)); \
        }                                                                            \
    } while (0)

    ISSUE_CHUNK(0, 0);
    CP_COMMIT();

    for (int kb = 0; kb < NKB; kb++) {
        const int st = kb & 1;
        if (kb + 1 < NKB) ISSUE_CHUNK((kb + 1) * KB, st ^ 1);
        CP_COMMIT();
        cp_wait<1>();
        __syncthreads();

        const uint32_t bA  = smem_base + (uint32_t)st*3*ARR_BYTES;
        const uint32_t bBh = bA +   ARR_BYTES;
        const uint32_t bBl = bA + 2*ARR_BYTES;

        #pragma unroll
        for (int ks = 0; ks < 2; ks++) {
            const uint32_t ko = (uint32_t)ks * 32;   // +16 halves = 32 bytes
            uint32_t ah[2][4];
            ldmatrix_x4(ah[0][0], ah[0][1], ah[0][2], ah[0][3], bA + aoffs + ko);
            ldmatrix_x4(ah[1][0], ah[1][1], ah[1][2], ah[1][3], bA + aoffs + ko + 16*(AS_STRIDE*2));

            #pragma unroll
            for (int p = 0; p < 4; p++) {
                uint32_t bh0, bh1, bh2, bh3, bl0, bl1, bl2, bl3;
                const uint32_t bo = boffs + ko + (uint32_t)p * (16*AS_STRIDE*2);
                ldmatrix_x4(bh0, bh1, bh2, bh3, bBh + bo);
                ldmatrix_x4(bl0, bl1, bl2, bl3, bBl + bo);
                #pragma unroll
                for (int mt = 0; mt < 2; mt++) {
                    mma16816(acc[mt][2*p],   ah[mt][0], ah[mt][1], ah[mt][2], ah[mt][3], bh0, bh1);
                    mma16816(acc[mt][2*p],   ah[mt][0], ah[mt][1], ah[mt][2], ah[mt][3], bl0, bl1);
                    mma16816(acc[mt][2*p+1], ah[mt][0], ah[mt][1], ah[mt][2], ah[mt][3], bh2, bh3);
                    mma16816(acc[mt][2*p+1], ah[mt][0], ah[mt][1], ah[mt][2], ah[mt][3], bl2, bl3);
                }
            }
        }
        __syncthreads();
    }
    #undef ISSUE_CHUNK

    // epilogue: fragment layout -> gmem with bias
    const int crow = lane >> 2;
    const int ccol = (lane & 3) * 2;
    #pragma unroll
    for (int mt = 0; mt < 2; mt++) {
        const int mbase = m0 + wm + mt*16 + crow;
        #pragma unroll
        for (int nt = 0; nt < 8; nt++) {
            const int n = n0 + wn + nt*8 + ccol;
            const float b0 = bias[n], b1 = bias[n+1];
            float2 r0 = make_float2(acc[mt][nt][0] + b0, acc[mt][nt][1] + b1);
            float2 r1 = make_float2(acc[mt][nt][2] + b0, acc[mt][nt][3] + b1);
            *reinterpret_cast<float2*>(&C[(size_t)mbase*N + n])     = r0;
            *reinterpret_cast<float2*>(&C[(size_t)(mbase+8)*N + n]) = r1;
        }
    }
}

// =====================================================================
// depthwise conv-4 (causal) + gating + transpose
// =====================================================================
__global__ __launch_bounds__(256) void convgate_kernel(
    const float* __restrict__ x1_s, const float* __restrict__ x2_s,
    const float* __restrict__ v_s,
    const float* __restrict__ x1_sb, const float* __restrict__ x2_sb,
    const float* __restrict__ v_sb)
{
    __shared__ float sh1[35*33];
    __shared__ float sh2[35*33];
    __shared__ float shv[35*33];
    const int tid = threadIdx.x;
    const int d0 = blockIdx.x * 32;
    const int l0 = blockIdx.y * 32;
    const int b  = blockIdx.z;

    for (int idx = tid; idx < 35*32; idx += 256) {
        const int r  = idx >> 5;
        const int cc = idx & 31;
        const int lg = l0 - 3 + r;
        float v1 = 0.f, v2 = 0.f, vv = 0.f;
        if (lg >= 0) {
            const size_t rowbase = ((size_t)(b*LL + lg)) * N3D + d0 + cc;
            v1 = g_xbuf[rowbase];
            v2 = g_xbuf[rowbase + DD];
            vv = g_xbuf[rowbase + 2*DD];
        }
        sh1[r*33 + cc] = v1;
        sh2[r*33 + cc] = v2;
        shv[r*33 + cc] = vv;
    }
    __syncthreads();

    #pragma unroll
    for (int t = 0; t < 4; t++) {
        const int o  = tid + t*256;
        const int dd = o >> 5;
        const int ll = o & 31;
        const int d  = d0 + dd;
        float c1 = x1_sb[d], c2 = x2_sb[d], cv = v_sb[d];
        #pragma unroll
        for (int j = 0; j < 4; j++) {
            const int r = ll + j;
            c1 += x1_s[d*4 + j] * sh1[r*33 + dd];
            c2 += x2_s[d*4 + j] * sh2[r*33 + dd];
            cv += v_s [d*4 + j] * shv[r*33 + dd];
        }
        const size_t out = ((size_t)(b*DD + d)) * LL + l0 + ll;
        g_vg [out] = cv * c1;
        g_x2g[out] = c2;
    }
}

// =====================================================================
// packed two-channel FFT convolution + D_bias + x2 gate
// CTA c handles channels d1=2*(c%384), d2=d1+1 of batch b=c/384 in ONE
// complex FFT (z = v1 + i*v2). Spectra unpacked via conjugate symmetry
// in bit-reversed order, multiplied by per-channel Kf, repacked, one
// inverse FFT: y1 = Re, y2 = Im.
// =====================================================================
__global__ __launch_bounds__(512) void fftconv2_kernel(const float* __restrict__ D_bias) {
    __shared__ float2 data[NFFT];
    __shared__ float2 tw[NFFT/2];
    const int c   = blockIdx.x;          // 0..3071
    const int b   = c / (DD/2);
    const int d1  = (c % (DD/2)) * 2;
    const int d2  = d1 + 1;
    const int tid = threadIdx.x;
    const size_t ch1 = ((size_t)b*DD + d1) * LL;
    const size_t ch2 = ch1 + LL;

    copy_tw(tw, tid);
    float v1c[4], v2c[4];
    #pragma unroll
    for (int i = 0; i < 4; i++) {
        const int l = tid + i*512;
        const float v1 = g_vg[ch1 + l];
        const float v2 = g_vg[ch2 + l];
        v1c[i] = v1; v2c[i] = v2;
        data[l]      = make_float2(v1, v2);
        data[l + LL] = make_float2(0.f, 0.f);
    }
    __syncthreads();

    fft_dif_fwd(data, tw, tid);          // ends with __syncthreads()

    // unpack spectra + per-channel multiply + repack (bit-reversed order)
    const float2* __restrict__ kf1 = &g_Kf[(size_t)d1 * NFFT];
    const float2* __restrict__ kf2 = &g_Kf[(size_t)d2 * NFFT];
    float2 Y[8];
    #pragma unroll
    for (int i = 0; i < 8; i++) {
        const int p = tid + i*512;
        const int f = (int)(__brev((unsigned)p) >> 20);           // rev12(p)
        const int q = (int)(__brev((unsigned)((NFFT - f) & (NFFT-1))) >> 20);
        const float2 Zp = data[p];
        const float2 Zq = data[q];
        // A = Zp + conj(Zq) -> V1 = A/2 ; B = Zp - conj(Zq) -> V2 = -iB/2
        const float2 V1 = make_float2(0.5f*(Zp.x + Zq.x), 0.5f*(Zp.y - Zq.y));
        const float2 V2 = make_float2(0.5f*(Zp.y + Zq.y), 0.5f*(Zq.x - Zp.x));
        const float2 C1 = cmul(V1, kf1[p]);
        const float2 C2 = cmul(V2, kf2[p]);
        Y[i] = make_float2(C1.x - C2.y, C1.y + C2.x);   // Y = C1 + i*C2
    }
    __syncthreads();
    #pragma unroll
    for (int i = 0; i < 8; i++) data[tid + i*512] = Y[i];
    __syncthreads();

    fft_dit_inv(data, tw, tid);          // ends with __syncthreads()

    const float db1 = D_bias[d1];
    const float db2 = D_bias[d2];
    #pragma unroll
    for (int i = 0; i < 4; i++) {
        const int l = tid + i*512;
        const float y1 = data[l].x * (1.0f / (float)NFFT);
        const float y2 = data[l].y * (1.0f / (float)NFFT);
        g_ybT[ch1 + l] = (y1 + v1c[i] * db1) * g_x2g[ch1 + l];
        g_ybT[ch2 + l] = (y2 + v2c[i] * db2) * g_x2g[ch2 + l];
    }
}

// =====================================================================
// launch  (gemm1 is deliberately the 4th launch: ncu captures launch #4)
// =====================================================================
extern "C" void kernel_launch(void* const* d_in, const int* in_sizes, int n_in,
                              void* d_out, int out_size) {
    const float* u      = (const float*)d_in[0];
    const float* in_W   = (const float*)d_in[1];
    const float* in_b   = (const float*)d_in[2];
    const float* out_W  = (const float*)d_in[3];
    const float* out_b  = (const float*)d_in[4];
    const float* x1_s   = (const float*)d_in[5];
    const float* x2_s   = (const float*)d_in[6];
    const float* v_s    = (const float*)d_in[7];
    const float* x1_sb  = (const float*)d_in[8];
    const float* x2_sb  = (const float*)d_in[9];
    const float* v_sb   = (const float*)d_in[10];
    const float* D_bias = (const float*)d_in[11];
    const float* z      = (const float*)d_in[12];
    const float* sfreq  = (const float*)d_in[13];
    const float* eo_mat = (const float*)d_in[14];
    const float* eo_b   = (const float*)d_in[15];
    const float* oo1    = (const float*)d_in[16];
    const float* oo1_b  = (const float*)d_in[17];
    const float* oo2    = (const float*)d_in[18];
    const float* oo2_b  = (const float*)d_in[19];
    const float* oh     = (const float*)d_in[20];
    float* out = (float*)d_out;

    float *xbuf, *ybT;
    __half *uh, *wh, *wl, *woh, *wol, *yh;
    cudaGetSymbolAddress((void**)&xbuf, g_xbuf);
    cudaGetSymbolAddress((void**)&ybT,  g_ybT);
    cudaGetSymbolAddress((void**)&uh,  g_uh);
    cudaGetSymbolAddress((void**)&wh,  g_wh);
    cudaGetSymbolAddress((void**)&wl,  g_wl);
    cudaGetSymbolAddress((void**)&woh, g_woh);
    cudaGetSymbolAddress((void**)&wol, g_wol);
    cudaGetSymbolAddress((void**)&yh,  g_yh);

    // (1-3) GEMM1 operand preps
    convert_kernel<<<(MM*DD/4 + 255)/256, 256>>>(u, uh, MM*DD/4);
    transpose_split_kernel<<<dim3(N3D/32, DD/32), 256>>>(in_W,  wh,  wl,  DD, N3D);
    transpose_split_kernel<<<dim3(DD/32,  DD/32), 256>>>(out_W, woh, wol, DD, DD);

    // (4) GEMM1: [16384 x 768] @ [768 x 2304]  <- ncu-captured launch
    gemm_mma_kernel<<<dim3(N3D/128, MM/128), 256>>>(uh, wh, wl, in_b, xbuf, DD, N3D);

    // (5-7) filter chain (independent of GEMM1)
    twinit_kernel<<<4, 512>>>();
    filter_kernel<<<LL/16, 128>>>(z, sfreq, eo_mat, eo_b, oo1, oo1_b, oo2, oo2_b, oh);
    fftk_kernel<<<DD, 512>>>();

    // (8-9) conv/gate + packed FFT convolution
    convgate_kernel<<<dim3(DD/32, LL/32, BB), 256>>>(x1_s, x2_s, v_s, x1_sb, x2_sb, v_sb);
    fftconv2_kernel<<<BB*DD/2, 512>>>(D_bias);

    // (10) y -> [(b,l)][d] fp16
    transpose_convert_kernel<<<dim3(LL/32, DD/32, BB), 256>>>(
        ybT, yh, DD, LL, (size_t)DD*LL);

    // (11) GEMM2: [16384 x 768] @ [768 x 768]
    gemm_mma_kernel<<<dim3(DD/128, MM/128), 256>>>(yh, woh, wol, out_b, out, DD, DD);
}

// round 9
// speedup vs baseline: 2.6777x; 1.2671x over previous
#include <cuda_runtime.h>
#include <cuda_bf16.h>
#include <cuda_fp16.h>
#include <math.h>
#include <stdint.h>

// Problem constants
#define BB   8
#define LL   2048
#define DD   768
#define ORD  128
#define NFFT 4096
#define MM   (BB*LL)          // 16384
#define N3D  (3*DD)           // 2304

#define MIN_DECAY (-3.0701134573253945f)
#define MAX_DECAY (-15.350567286626972f)

// ---------------- scratch (device globals; no allocations allowed) ------------
__device__ float  g_k[DD * LL];            // filter k[d][l]
__device__ float2 g_Kf[DD * NFFT];         // FFT(k) in radix-4 digit-reversed order
__device__ float2 g_tw[NFFT/4];            // twiddle table exp(-2*pi*i*j/4096), j<1024
__device__ float  g_xbuf[(size_t)MM * N3D];// u @ in_W + b   [m][c]
__device__ float  g_vg [BB * DD * LL];     // conv(v)*conv(x1), channel-major
__device__ float  g_x2g[BB * DD * LL];     // conv(x2), channel-major
__device__ float  g_ybT[BB * DD * LL];     // gated fftconv output, channel-major

// fp16 operands for tensor-core GEMMs (A single, B hi/lo split)
__device__ __half g_uh[(size_t)MM * DD];    // u as fp16        [m][k]
__device__ __half g_wh[(size_t)N3D * DD];   // in_W^T hi        [N][K]
__device__ __half g_wl[(size_t)N3D * DD];   // in_W^T lo
__device__ __half g_woh[(size_t)DD * DD];   // out_W^T hi       [N][K]
__device__ __half g_wol[(size_t)DD * DD];   // out_W^T lo
__device__ __half g_yh[(size_t)MM * DD];    // gated y as fp16  [m][k]

__device__ __forceinline__ float2 cmul(float2 a, float2 b) {
    return make_float2(a.x*b.x - a.y*b.y, a.x*b.y + a.y*b.x);
}
__device__ __forceinline__ float2 cadd(float2 a, float2 b) {
    return make_float2(a.x + b.x, a.y + b.y);
}
__device__ __forceinline__ float2 csub(float2 a, float2 b) {
    return make_float2(a.x - b.x, a.y - b.y);
}

// ============================ mma helpers ====================================
__device__ __forceinline__ uint32_t smem_u32(const void* p) {
    uint32_t a;
    asm("{ .reg .u64 t; cvta.to.shared.u64 t, %1; cvt.u32.u64 %0, t; }" : "=r"(a) : "l"(p));
    return a;
}
__device__ __forceinline__ void ldmatrix_x4(uint32_t &r0, uint32_t &r1,
                                            uint32_t &r2, uint32_t &r3,
                                            uint32_t addr) {
    asm volatile("ldmatrix.sync.aligned.m8n8.x4.shared.b16 {%0,%1,%2,%3}, [%4];"
                 : "=r"(r0), "=r"(r1), "=r"(r2), "=r"(r3) : "r"(addr));
}
__device__ __forceinline__ void mma16816(float* c,
                                         uint32_t a0, uint32_t a1, uint32_t a2, uint32_t a3,
                                         uint32_t b0, uint32_t b1) {
    asm volatile("mma.sync.aligned.m16n8k16.row.col.f32.f16.f16.f32 "
                 "{%0,%1,%2,%3}, {%4,%5,%6,%7}, {%8,%9}, {%0,%1,%2,%3};"
                 : "+f"(c[0]), "+f"(c[1]), "+f"(c[2]), "+f"(c[3])
                 : "r"(a0), "r"(a1), "r"(a2), "r"(a3), "r"(b0), "r"(b1));
}
#define CP_ASYNC16(dst, src) \
    asm volatile("cp.async.cg.shared.global [%0], [%1], 16;" :: "r"(dst), "l"(src))
#define CP_COMMIT() asm volatile("cp.async.commit_group;" ::: "memory")
template<int N>
__device__ __forceinline__ void cp_wait() {
    asm volatile("cp.async.wait_group %0;" :: "n"(N) : "memory");
}

// =====================================================================
// twiddle table (1024 entries)
// =====================================================================
__global__ __launch_bounds__(512) void twinit_kernel() {
    const int j = blockIdx.x * 512 + threadIdx.x;
    if (j < NFFT/4) {
        float s, c;
        sincospif(-(float)j / 2048.0f, &s, &c);   // exp(-i*2*pi*j/4096)
        g_tw[j] = make_float2(c, s);
    }
}

// =====================================================================
// Hyena filter  ->  g_k[d][l]
// =====================================================================
__global__ __launch_bounds__(128) void filter_kernel(
    const float* __restrict__ z, const float* __restrict__ sin_freq,
    const float* __restrict__ eo_mat, const float* __restrict__ eo_bias,
    const float* __restrict__ oo1, const float* __restrict__ oo1_b,
    const float* __restrict__ oo2, const float* __restrict__ oo2_b,
    const float* __restrict__ oh)
{
    __shared__ float hA[16][129];
    __shared__ float hB[16][129];
    const int o  = threadIdx.x;
    const int l0 = blockIdx.x * 16;
    const float f = sin_freq[o];

    #pragma unroll 1
    for (int l = 0; l < 16; l++) {
        float acc = eo_bias[o];
        #pragma unroll
        for (int e = 0; e < 5; e++) acc += z[(l0+l)*5 + e] * eo_mat[e*ORD + o];
        hA[l][o] = sinf(f * acc);
    }
    __syncthreads();
    #pragma unroll 1
    for (int l = 0; l < 16; l++) {
        float acc = oo1_b[o];
        #pragma unroll 4
        for (int p = 0; p < ORD; p++) acc += hA[l][p] * oo1[p*ORD + o];
        hB[l][o] = sinf(f * acc);
    }
    __syncthreads();
    #pragma unroll 1
    for (int l = 0; l < 16; l++) {
        float acc = oo2_b[o];
        #pragma unroll 4
        for (int p = 0; p < ORD; p++) acc += hB[l][p] * oo2[p*ORD + o];
        hA[l][o] = sinf(f * acc);
    }
    __syncthreads();
    #pragma unroll 1
    for (int c = 0; c < DD/ORD; c++) {
        const int d = o + c * ORD;
        float acc[16];
        #pragma unroll
        for (int l = 0; l < 16; l++) acc[l] = 0.f;
        #pragma unroll 2
        for (int p = 0; p < ORD; p++) {
            const float w = oh[p*DD + d];
            #pragma unroll
            for (int l = 0; l < 16; l++) acc[l] += hA[l][p] * w;
        }
        const float delta = fabsf(MIN_DECAY + (MAX_DECAY - MIN_DECAY) * ((float)d / 767.0f));
        #pragma unroll
        for (int l = 0; l < 16; l++) {
            const int lg = l0 + l;
            const float t = (float)lg / 2047.0f;
            g_k[d*LL + lg] = acc[l] * expf(-t * delta);
        }
    }
}

// =====================================================================
// radix-4 FFT helpers (512 threads per CTA, N=4096 -> 6 stages each way)
// forward = DIF radix-4 (natural -> base-4 digit-reversed)
// inverse = mirrored DIT radix-4 w/ conj twiddles (digit-reversed -> natural),
//           unscaled (total factor N)
// =====================================================================
__device__ __forceinline__ void copy_tw(float2* tw, int tid) {
    #pragma unroll
    for (int j = tid; j < NFFT/4; j += 512) tw[j] = g_tw[j];
}

__device__ void fft4_fwd(float2* data, const float2* tw, int tid) {
    #pragma unroll
    for (int s2 = 10; s2 >= 0; s2 -= 2) {
        const int m    = 1 << s2;
        const int step = 1024 >> s2;     // 1024/m
        #pragma unroll
        for (int t = 0; t < 2; t++) {
            const int idx  = tid + t * 512;          // 0..1023
            const int j    = idx & (m - 1);
            const int base = ((idx >> s2) << (s2 + 2)) + j;
            const float2 x0 = data[base];
            const float2 x1 = data[base + m];
            const float2 x2 = data[base + 2*m];
            const float2 x3 = data[base + 3*m];
            const float2 a  = cadd(x0, x2);
            const float2 b  = csub(x0, x2);
            const float2 c  = cadd(x1, x3);
            const float2 d  = csub(x1, x3);
            const float2 di = make_float2(d.y, -d.x);      // -i*d
            const float2 w1 = tw[j * step];
            const float2 w2 = cmul(w1, w1);
            const float2 w3 = cmul(w1, w2);
            data[base]       = cadd(a, c);
            data[base + m]   = cmul(cadd(b, di), w1);
            data[base + 2*m] = cmul(csub(a, c), w2);
            data[base + 3*m] = cmul(csub(b, di), w3);
        }
        __syncthreads();
    }
}

__device__ void fft4_inv(float2* data, const float2* tw, int tid) {
    #pragma unroll
    for (int s2 = 0; s2 <= 10; s2 += 2) {
        const int m    = 1 << s2;
        const int step = 1024 >> s2;
        #pragma unroll
        for (int t = 0; t < 2; t++) {
            const int idx  = tid + t * 512;
            const int j    = idx & (m - 1);
            const int base = ((idx >> s2) << (s2 + 2)) + j;
            float2 w1 = tw[j * step];
            w1.y = -w1.y;                                   // conj
            const float2 w2 = cmul(w1, w1);
            const float2 w3 = cmul(w1, w2);
            const float2 z0 = data[base];
            const float2 z1 = cmul(data[base + m],   w1);
            const float2 z2 = cmul(data[base + 2*m], w2);
            const float2 z3 = cmul(data[base + 3*m], w3);
            const float2 s02 = cadd(z0, z2);
            const float2 d02 = csub(z0, z2);
            const float2 s13 = cadd(z1, z3);
            const float2 d13 = csub(z1, z3);
            data[base]       = cadd(s02, s13);
            data[base + 2*m] = csub(s02, s13);
            // x1 = d02 + i*d13 ; x3 = d02 - i*d13
            data[base + m]   = make_float2(d02.x - d13.y, d02.y + d13.x);
            data[base + 3*m] = make_float2(d02.x + d13.y, d02.y - d13.x);
        }
        __syncthreads();
    }
}

// base-4 digit reversal of a 12-bit index (involution)
__device__ __forceinline__ int rev4_12(int x) {
    const int r = (int)(__brev((unsigned)x) >> 20);         // bitrev12
    return ((r & 0x555) << 1) | ((r >> 1) & 0x555);         // swap adjacent bits
}

// =====================================================================
// FFT of filter k  ->  g_Kf (radix-4 digit-reversed order)
// =====================================================================
__global__ __launch_bounds__(512) void fftk_kernel() {
    __shared__ float2 data[NFFT];
    __shared__ float2 tw[NFFT/4];
    const int d = blockIdx.x;
    const int tid = threadIdx.x;
    copy_tw(tw, tid);
    #pragma unroll
    for (int i = tid; i < LL; i += 512) {
        data[i]      = make_float2(g_k[d*LL + i], 0.f);
        data[i + LL] = make_float2(0.f, 0.f);
    }
    __syncthreads();
    fft4_fwd(data, tw, tid);
    #pragma unroll
    for (int i = tid; i < NFFT; i += 512) g_Kf[(size_t)d*NFFT + i] = data[i];
}

// =====================================================================
// Prep: convert fp32 -> fp16 (same layout)
// =====================================================================
__global__ __launch_bounds__(256) void convert_kernel(
    const float* __restrict__ in, __half* __restrict__ out, int n4)
{
    const int i = blockIdx.x * 256 + threadIdx.x;
    if (i >= n4) return;
    const float4 v = reinterpret_cast<const float4*>(in)[i];
    reinterpret_cast<__half2*>(out)[i*2]   = __floats2half2_rn(v.x, v.y);
    reinterpret_cast<__half2*>(out)[i*2+1] = __floats2half2_rn(v.z, v.w);
}

// =====================================================================
// Prep: transpose [R][C] fp32 -> [C][R] fp16 hi/lo (weights)
// =====================================================================
__global__ __launch_bounds__(256) void transpose_split_kernel(
    const float* __restrict__ in, __half* __restrict__ oh,
    __half* __restrict__ ol, int R, int C)
{
    __shared__ float tile[32][33];
    const int r0 = blockIdx.y * 32, c0 = blockIdx.x * 32;
    const int tx = threadIdx.x & 31, ty = threadIdx.x >> 5;
    #pragma unroll
    for (int i = 0; i < 32; i += 8)
        tile[ty+i][tx] = in[(size_t)(r0+ty+i)*C + c0 + tx];
    __syncthreads();
    #pragma unroll
    for (int i = 0; i < 32; i += 8) {
        const float x = tile[tx][ty+i];
        const __half h = __float2half_rn(x);
        const __half l = __float2half_rn(x - __half2float(h));
        const size_t o = (size_t)(c0+ty+i)*R + r0 + tx;
        oh[o] = h;
        ol[o] = l;
    }
}

// =====================================================================
// Prep: transpose [b][R][C] fp32 -> [b][C][R] fp16 (activation y)
// =====================================================================
__global__ __launch_bounds__(256) void transpose_convert_kernel(
    const float* __restrict__ in, __half* __restrict__ out, int R, int C,
    size_t batchStride)
{
    __shared__ float tile[32][33];
    const int b  = blockIdx.z;
    const float* src = in + (size_t)b * batchStride;
    const int r0 = blockIdx.y * 32, c0 = blockIdx.x * 32;
    const int tx = threadIdx.x & 31, ty = threadIdx.x >> 5;
    #pragma unroll
    for (int i = 0; i < 32; i += 8)
        tile[ty+i][tx] = src[(size_t)(r0+ty+i)*C + c0 + tx];
    __syncthreads();
    #pragma unroll
    for (int i = 0; i < 32; i += 8) {
        const size_t o = (size_t)b*batchStride + (size_t)(c0+ty+i)*R + r0 + tx;
        out[o] = __float2half_rn(tile[tx][ty+i]);
    }
}

// =====================================================================
// mma.sync GEMM: C[M][N] = A[M][K] @ (Bh+Bl)[N][K]^T + bias
// A fp16; B fp16 hi/lo -> 2 mma passes. cp.async 2-stage pipeline.
// CTA tile 128x128, 8 warps (32m x 64n each), K-chunks of 32.
// =====================================================================
#define KB       32                   // K halves per chunk
#define AS_STRIDE 40                  // halves per smem row (32 data + 8 pad)
#define ARR_BYTES (128*AS_STRIDE*2)   // 10240 B per array

__global__ __launch_bounds__(256, 2) void gemm_mma_kernel(
    const __half* __restrict__ A,
    const __half* __restrict__ Bh, const __half* __restrict__ Bl,
    const float* __restrict__ bias, float* __restrict__ C,
    int K, int N)
{
    // 2 stages x 3 arrays (A, BH, BL) x 10240 B = 61440 B
    __shared__ __align__(16) __half smbuf[2*3*128*AS_STRIDE];
    const uint32_t smem_base = smem_u32(smbuf);

    const int tid  = threadIdx.x;
    const int wid  = tid >> 5;
    const int lane = tid & 31;
    const int m0 = blockIdx.y * 128;
    const int n0 = blockIdx.x * 128;
    const int wm = (wid & 3) * 32;   // warp m offset in tile
    const int wn = (wid >> 2) * 64;  // warp n offset in tile

    // copy mapping: 512 16B-segments per array, 2 per thread
    const int r0s = tid >> 2;
    const int p0s = tid & 3;

    // ldmatrix per-lane offsets (bytes, within one array)
    const int arow  = wm + (lane & 15);
    const uint32_t aoffs = (uint32_t)arow * (AS_STRIDE*2) + (uint32_t)(lane >> 4) * 16;
    const int brow  = wn + (lane & 7) + ((lane >> 4) & 1) * 8;
    const uint32_t boffs = (uint32_t)brow * (AS_STRIDE*2) + (uint32_t)((lane >> 3) & 1) * 16;

    float acc[2][8][4];
    #pragma unroll
    for (int i = 0; i < 2; i++)
        #pragma unroll
        for (int j = 0; j < 8; j++)
            #pragma unroll
            for (int q = 0; q < 4; q++) acc[i][j][q] = 0.f;

    const int NKB = K / KB;   // 24

    #define ISSUE_CHUNK(k0, st) do {                                                 \
        const uint32_t sbase = smem_base + (uint32_t)(st)*3*ARR_BYTES;               \
        _Pragma("unroll")                                                            \
        for (int t = 0; t < 2; t++) {                                                \
            const int row  = r0s + t*64;                                             \
            const int kk   = (k0) + p0s*8;                                           \
            const uint32_t dst = sbase + (uint32_t)row*(AS_STRIDE*2) + p0s*16;       \
            CP_ASYNC16(dst,               (const char*)(A  + (size_t)(m0+row)*K + kk)); \
            CP_ASYNC16(dst +   ARR_BYTES, (const char*)(Bh + (size_t)(n0+row)*K + kk)); \
            CP_ASYNC16(dst + 2*ARR_BYTES, (const char*)(Bl + (size_t)(n0+row)*K + kk)); \
        }                                                                            \
    } while (0)

    ISSUE_CHUNK(0, 0);
    CP_COMMIT();

    for (int kb = 0; kb < NKB; kb++) {
        const int st = kb & 1;
        if (kb + 1 < NKB) ISSUE_CHUNK((kb + 1) * KB, st ^ 1);
        CP_COMMIT();
        cp_wait<1>();
        __syncthreads();

        const uint32_t bA  = smem_base + (uint32_t)st*3*ARR_BYTES;
        const uint32_t bBh = bA +   ARR_BYTES;
        const uint32_t bBl = bA + 2*ARR_BYTES;

        #pragma unroll
        for (int ks = 0; ks < 2; ks++) {
            const uint32_t ko = (uint32_t)ks * 32;   // +16 halves = 32 bytes
            uint32_t ah[2][4];
            ldmatrix_x4(ah[0][0], ah[0][1], ah[0][2], ah[0][3], bA + aoffs + ko);
            ldmatrix_x4(ah[1][0], ah[1][1], ah[1][2], ah[1][3], bA + aoffs + ko + 16*(AS_STRIDE*2));

            #pragma unroll
            for (int p = 0; p < 4; p++) {
                uint32_t bh0, bh1, bh2, bh3, bl0, bl1, bl2, bl3;
                const uint32_t bo = boffs + ko + (uint32_t)p * (16*AS_STRIDE*2);
                ldmatrix_x4(bh0, bh1, bh2, bh3, bBh + bo);
                ldmatrix_x4(bl0, bl1, bl2, bl3, bBl + bo);
                #pragma unroll
                for (int mt = 0; mt < 2; mt++) {
                    mma16816(acc[mt][2*p],   ah[mt][0], ah[mt][1], ah[mt][2], ah[mt][3], bh0, bh1);
                    mma16816(acc[mt][2*p],   ah[mt][0], ah[mt][1], ah[mt][2], ah[mt][3], bl0, bl1);
                    mma16816(acc[mt][2*p+1], ah[mt][0], ah[mt][1], ah[mt][2], ah[mt][3], bh2, bh3);
                    mma16816(acc[mt][2*p+1], ah[mt][0], ah[mt][1], ah[mt][2], ah[mt][3], bl2, bl3);
                }
            }
        }
        __syncthreads();
    }
    #undef ISSUE_CHUNK

    // epilogue: fragment layout -> gmem with bias
    const int crow = lane >> 2;
    const int ccol = (lane & 3) * 2;
    #pragma unroll
    for (int mt = 0; mt < 2; mt++) {
        const int mbase = m0 + wm + mt*16 + crow;
        #pragma unroll
        for (int nt = 0; nt < 8; nt++) {
            const int n = n0 + wn + nt*8 + ccol;
            const float b0 = bias[n], b1 = bias[n+1];
            float2 r0 = make_float2(acc[mt][nt][0] + b0, acc[mt][nt][1] + b1);
            float2 r1 = make_float2(acc[mt][nt][2] + b0, acc[mt][nt][3] + b1);
            *reinterpret_cast<float2*>(&C[(size_t)mbase*N + n])     = r0;
            *reinterpret_cast<float2*>(&C[(size_t)(mbase+8)*N + n]) = r1;
        }
    }
}

// =====================================================================
// depthwise conv-4 (causal) + gating + transpose
// =====================================================================
__global__ __launch_bounds__(256) void convgate_kernel(
    const float* __restrict__ x1_s, const float* __restrict__ x2_s,
    const float* __restrict__ v_s,
    const float* __restrict__ x1_sb, const float* __restrict__ x2_sb,
    const float* __restrict__ v_sb)
{
    __shared__ float sh1[35*33];
    __shared__ float sh2[35*33];
    __shared__ float shv[35*33];
    const int tid = threadIdx.x;
    const int d0 = blockIdx.x * 32;
    const int l0 = blockIdx.y * 32;
    const int b  = blockIdx.z;

    for (int idx = tid; idx < 35*32; idx += 256) {
        const int r  = idx >> 5;
        const int cc = idx & 31;
        const int lg = l0 - 3 + r;
        float v1 = 0.f, v2 = 0.f, vv = 0.f;
        if (lg >= 0) {
            const size_t rowbase = ((size_t)(b*LL + lg)) * N3D + d0 + cc;
            v1 = g_xbuf[rowbase];
            v2 = g_xbuf[rowbase + DD];
            vv = g_xbuf[rowbase + 2*DD];
        }
        sh1[r*33 + cc] = v1;
        sh2[r*33 + cc] = v2;
        shv[r*33 + cc] = vv;
    }
    __syncthreads();

    #pragma unroll
    for (int t = 0; t < 4; t++) {
        const int o  = tid + t*256;
        const int dd = o >> 5;
        const int ll = o & 31;
        const int d  = d0 + dd;
        float c1 = x1_sb[d], c2 = x2_sb[d], cv = v_sb[d];
        #pragma unroll
        for (int j = 0; j < 4; j++) {
            const int r = ll + j;
            c1 += x1_s[d*4 + j] * sh1[r*33 + dd];
            c2 += x2_s[d*4 + j] * sh2[r*33 + dd];
            cv += v_s [d*4 + j] * shv[r*33 + dd];
        }
        const size_t out = ((size_t)(b*DD + d)) * LL + l0 + ll;
        g_vg [out] = cv * c1;
        g_x2g[out] = c2;
    }
}

// =====================================================================
// packed two-channel radix-4 FFT convolution + D_bias + x2 gate
// CTA c handles channels d1=2*(c%384), d2=d1+1 of batch b=c/384 in ONE
// complex FFT (z = v1 + i*v2). Spectra unpacked via conjugate symmetry
// in base-4 digit-reversed order, multiplied by per-channel Kf, repacked,
// one inverse FFT: y1 = Re, y2 = Im.
// =====================================================================
__global__ __launch_bounds__(512) void fftconv2_kernel(const float* __restrict__ D_bias) {
    __shared__ float2 data[NFFT];
    __shared__ float2 tw[NFFT/4];
    const int c   = blockIdx.x;          // 0..3071
    const int b   = c / (DD/2);
    const int d1  = (c % (DD/2)) * 2;
    const int d2  = d1 + 1;
    const int tid = threadIdx.x;
    const size_t ch1 = ((size_t)b*DD + d1) * LL;
    const size_t ch2 = ch1 + LL;

    copy_tw(tw, tid);
    float v1c[4], v2c[4];
    #pragma unroll
    for (int i = 0; i < 4; i++) {
        const int l = tid + i*512;
        const float v1 = g_vg[ch1 + l];
        const float v2 = g_vg[ch2 + l];
        v1c[i] = v1; v2c[i] = v2;
        data[l]      = make_float2(v1, v2);
        data[l + LL] = make_float2(0.f, 0.f);
    }
    __syncthreads();

    fft4_fwd(data, tw, tid);             // ends with __syncthreads()

    // unpack spectra + per-channel multiply + repack (digit-reversed order)
    const float2* __restrict__ kf1 = &g_Kf[(size_t)d1 * NFFT];
    const float2* __restrict__ kf2 = &g_Kf[(size_t)d2 * NFFT];
    float2 Y[8];
    #pragma unroll
    for (int i = 0; i < 8; i++) {
        const int p = tid + i*512;
        const int f = rev4_12(p);                       // frequency at position p
        const int q = rev4_12((NFFT - f) & (NFFT-1));   // position of freq N-f
        const float2 Zp = data[p];
        const float2 Zq = data[q];
        // V1 = (Zp + conj(Zq))/2 ; V2 = (Zp - conj(Zq))/(2i)
        const float2 V1 = make_float2(0.5f*(Zp.x + Zq.x), 0.5f*(Zp.y - Zq.y));
        const float2 V2 = make_float2(0.5f*(Zp.y + Zq.y), 0.5f*(Zq.x - Zp.x));
        const float2 C1 = cmul(V1, kf1[p]);
        const float2 C2 = cmul(V2, kf2[p]);
        Y[i] = make_float2(C1.x - C2.y, C1.y + C2.x);   // Y = C1 + i*C2
    }
    __syncthreads();
    #pragma unroll
    for (int i = 0; i < 8; i++) data[tid + i*512] = Y[i];
    __syncthreads();

    fft4_inv(data, tw, tid);             // ends with __syncthreads()

    const float db1 = D_bias[d1];
    const float db2 = D_bias[d2];
    #pragma unroll
    for (int i = 0; i < 4; i++) {
        const int l = tid + i*512;
        const float y1 = data[l].x * (1.0f / (float)NFFT);
        const float y2 = data[l].y * (1.0f / (float)NFFT);
        g_ybT[ch1 + l] = (y1 + v1c[i] * db1) * g_x2g[ch1 + l];
        g_ybT[ch2 + l] = (y2 + v2c[i] * db2) * g_x2g[ch2 + l];
    }
}

// =====================================================================
// launch  (gemm1 is deliberately the 4th launch: ncu captures launch #4)
// =====================================================================
extern "C" void kernel_launch(void* const* d_in, const int* in_sizes, int n_in,
                              void* d_out, int out_size) {
    const float* u      = (const float*)d_in[0];
    const float* in_W   = (const float*)d_in[1];
    const float* in_b   = (const float*)d_in[2];
    const float* out_W  = (const float*)d_in[3];
    const float* out_b  = (const float*)d_in[4];
    const float* x1_s   = (const float*)d_in[5];
    const float* x2_s   = (const float*)d_in[6];
    const float* v_s    = (const float*)d_in[7];
    const float* x1_sb  = (const float*)d_in[8];
    const float* x2_sb  = (const float*)d_in[9];
    const float* v_sb   = (const float*)d_in[10];
    const float* D_bias = (const float*)d_in[11];
    const float* z      = (const float*)d_in[12];
    const float* sfreq  = (const float*)d_in[13];
    const float* eo_mat = (const float*)d_in[14];
    const float* eo_b   = (const float*)d_in[15];
    const float* oo1    = (const float*)d_in[16];
    const float* oo1_b  = (const float*)d_in[17];
    const float* oo2    = (const float*)d_in[18];
    const float* oo2_b  = (const float*)d_in[19];
    const float* oh     = (const float*)d_in[20];
    float* out = (float*)d_out;

    float *xbuf, *ybT;
    __half *uh, *wh, *wl, *woh, *wol, *yh;
    cudaGetSymbolAddress((void**)&xbuf, g_xbuf);
    cudaGetSymbolAddress((void**)&ybT,  g_ybT);
    cudaGetSymbolAddress((void**)&uh,  g_uh);
    cudaGetSymbolAddress((void**)&wh,  g_wh);
    cudaGetSymbolAddress((void**)&wl,  g_wl);
    cudaGetSymbolAddress((void**)&woh, g_woh);
    cudaGetSymbolAddress((void**)&wol, g_wol);
    cudaGetSymbolAddress((void**)&yh,  g_yh);

    // (1-3) GEMM1 operand preps
    convert_kernel<<<(MM*DD/4 + 255)/256, 256>>>(u, uh, MM*DD/4);
    transpose_split_kernel<<<dim3(N3D/32, DD/32), 256>>>(in_W,  wh,  wl,  DD, N3D);
    transpose_split_kernel<<<dim3(DD/32,  DD/32), 256>>>(out_W, woh, wol, DD, DD);

    // (4) GEMM1: [16384 x 768] @ [768 x 2304]  <- ncu-captured launch
    gemm_mma_kernel<<<dim3(N3D/128, MM/128), 256>>>(uh, wh, wl, in_b, xbuf, DD, N3D);

    // (5-7) filter chain (independent of GEMM1)
    twinit_kernel<<<2, 512>>>();
    filter_kernel<<<LL/16, 128>>>(z, sfreq, eo_mat, eo_b, oo1, oo1_b, oo2, oo2_b, oh);
    fftk_kernel<<<DD, 512>>>();

    // (8-9) conv/gate + packed radix-4 FFT convolution
    convgate_kernel<<<dim3(DD/32, LL/32, BB), 256>>>(x1_s, x2_s, v_s, x1_sb, x2_sb, v_sb);
    fftconv2_kernel<<<BB*DD/2, 512>>>(D_bias);

    // (10) y -> [(b,l)][d] fp16
    transpose_convert_kernel<<<dim3(LL/32, DD/32, BB), 256>>>(
        ybT, yh, DD, LL, (size_t)DD*LL);

    // (11) GEMM2: [16384 x 768] @ [768 x 768]
    gemm_mma_kernel<<<dim3(DD/128, MM/128), 256>>>(yh, woh, wol, out_b, out, DD, DD);
}

// round 10
// speedup vs baseline: 2.7936x; 1.0433x over previous
#include <cuda_runtime.h>
#include <cuda_bf16.h>
#include <cuda_fp16.h>
#include <math.h>
#include <stdint.h>

// Problem constants
#define BB   8
#define LL   2048
#define DD   768
#define ORD  128
#define NFFT 4096
#define MM   (BB*LL)          // 16384
#define N3D  (3*DD)           // 2304

#define MIN_DECAY (-3.0701134573253945f)
#define MAX_DECAY (-15.350567286626972f)

// ---------------- scratch (device globals; no allocations allowed) ------------
__device__ float  g_k[DD * LL];            // filter k[d][l]
__device__ float2 g_Kf[DD * NFFT];         // FFT(k) in radix-4 digit-reversed order
__device__ float2 g_tw[NFFT/4];            // twiddle table exp(-2*pi*i*j/4096), j<1024
__device__ float  g_xbuf[(size_t)MM * N3D];// u @ in_W + b   [m][c]
__device__ float  g_vg [BB * DD * LL];     // conv(v)*conv(x1), channel-major
__device__ float  g_x2g[BB * DD * LL];     // conv(x2), channel-major
__device__ float  g_ybT[BB * DD * LL];     // gated fftconv output, channel-major

// fp16 operands for tensor-core GEMMs (A single, B hi/lo split)
__device__ __half g_uh[(size_t)MM * DD];    // u as fp16        [m][k]
__device__ __half g_wh[(size_t)N3D * DD];   // in_W^T hi        [N][K]
__device__ __half g_wl[(size_t)N3D * DD];   // in_W^T lo
__device__ __half g_woh[(size_t)DD * DD];   // out_W^T hi       [N][K]
__device__ __half g_wol[(size_t)DD * DD];   // out_W^T lo
__device__ __half g_yh[(size_t)MM * DD];    // gated y as fp16  [m][k]

__device__ __forceinline__ float2 cmul(float2 a, float2 b) {
    return make_float2(a.x*b.x - a.y*b.y, a.x*b.y + a.y*b.x);
}
__device__ __forceinline__ float2 cadd(float2 a, float2 b) {
    return make_float2(a.x + b.x, a.y + b.y);
}
__device__ __forceinline__ float2 csub(float2 a, float2 b) {
    return make_float2(a.x - b.x, a.y - b.y);
}

// ============================ mma helpers ====================================
__device__ __forceinline__ uint32_t smem_u32(const void* p) {
    uint32_t a;
    asm("{ .reg .u64 t; cvta.to.shared.u64 t, %1; cvt.u32.u64 %0, t; }" : "=r"(a) : "l"(p));
    return a;
}
__device__ __forceinline__ void ldmatrix_x4(uint32_t &r0, uint32_t &r1,
                                            uint32_t &r2, uint32_t &r3,
                                            uint32_t addr) {
    asm volatile("ldmatrix.sync.aligned.m8n8.x4.shared.b16 {%0,%1,%2,%3}, [%4];"
                 : "=r"(r0), "=r"(r1), "=r"(r2), "=r"(r3) : "r"(addr));
}
__device__ __forceinline__ void mma16816(float* c,
                                         uint32_t a0, uint32_t a1, uint32_t a2, uint32_t a3,
                                         uint32_t b0, uint32_t b1) {
    asm volatile("mma.sync.aligned.m16n8k16.row.col.f32.f16.f16.f32 "
                 "{%0,%1,%2,%3}, {%4,%5,%6,%7}, {%8,%9}, {%0,%1,%2,%3};"
                 : "+f"(c[0]), "+f"(c[1]), "+f"(c[2]), "+f"(c[3])
                 : "r"(a0), "r"(a1), "r"(a2), "r"(a3), "r"(b0), "r"(b1));
}
#define CP_ASYNC16(dst, src) \
    asm volatile("cp.async.cg.shared.global [%0], [%1], 16;" :: "r"(dst), "l"(src))
#define CP_COMMIT() asm volatile("cp.async.commit_group;" ::: "memory")
template<int N>
__device__ __forceinline__ void cp_wait() {
    asm volatile("cp.async.wait_group %0;" :: "n"(N) : "memory");
}

// =====================================================================
// twiddle table (1024 entries)
// =====================================================================
__global__ __launch_bounds__(512) void twinit_kernel() {
    const int j = blockIdx.x * 512 + threadIdx.x;
    if (j < NFFT/4) {
        float s, c;
        sincospif(-(float)j / 2048.0f, &s, &c);   // exp(-i*2*pi*j/4096)
        g_tw[j] = make_float2(c, s);
    }
}

// =====================================================================
// Hyena filter  ->  g_k[d][l]
// =====================================================================
__global__ __launch_bounds__(128) void filter_kernel(
    const float* __restrict__ z, const float* __restrict__ sin_freq,
    const float* __restrict__ eo_mat, const float* __restrict__ eo_bias,
    const float* __restrict__ oo1, const float* __restrict__ oo1_b,
    const float* __restrict__ oo2, const float* __restrict__ oo2_b,
    const float* __restrict__ oh)
{
    __shared__ float hA[16][129];
    __shared__ float hB[16][129];
    const int o  = threadIdx.x;
    const int l0 = blockIdx.x * 16;
    const float f = sin_freq[o];

    #pragma unroll 1
    for (int l = 0; l < 16; l++) {
        float acc = eo_bias[o];
        #pragma unroll
        for (int e = 0; e < 5; e++) acc += z[(l0+l)*5 + e] * eo_mat[e*ORD + o];
        hA[l][o] = sinf(f * acc);
    }
    __syncthreads();
    #pragma unroll 1
    for (int l = 0; l < 16; l++) {
        float acc = oo1_b[o];
        #pragma unroll 4
        for (int p = 0; p < ORD; p++) acc += hA[l][p] * oo1[p*ORD + o];
        hB[l][o] = sinf(f * acc);
    }
    __syncthreads();
    #pragma unroll 1
    for (int l = 0; l < 16; l++) {
        float acc = oo2_b[o];
        #pragma unroll 4
        for (int p = 0; p < ORD; p++) acc += hB[l][p] * oo2[p*ORD + o];
        hA[l][o] = sinf(f * acc);
    }
    __syncthreads();
    #pragma unroll 1
    for (int c = 0; c < DD/ORD; c++) {
        const int d = o + c * ORD;
        float acc[16];
        #pragma unroll
        for (int l = 0; l < 16; l++) acc[l] = 0.f;
        #pragma unroll 2
        for (int p = 0; p < ORD; p++) {
            const float w = oh[p*DD + d];
            #pragma unroll
            for (int l = 0; l < 16; l++) acc[l] += hA[l][p] * w;
        }
        const float delta = fabsf(MIN_DECAY + (MAX_DECAY - MIN_DECAY) * ((float)d / 767.0f));
        #pragma unroll
        for (int l = 0; l < 16; l++) {
            const int lg = l0 + l;
            const float t = (float)lg / 2047.0f;
            g_k[d*LL + lg] = acc[l] * expf(-t * delta);
        }
    }
}

// =====================================================================
// radix-4 FFT helpers (512 threads per CTA, N=4096 -> 6 stages each way)
// =====================================================================
__device__ __forceinline__ void copy_tw(float2* tw, int tid) {
    #pragma unroll
    for (int j = tid; j < NFFT/4; j += 512) tw[j] = g_tw[j];
}

__device__ void fft4_fwd(float2* data, const float2* tw, int tid) {
    #pragma unroll
    for (int s2 = 10; s2 >= 0; s2 -= 2) {
        const int m    = 1 << s2;
        const int step = 1024 >> s2;     // 1024/m
        #pragma unroll
        for (int t = 0; t < 2; t++) {
            const int idx  = tid + t * 512;          // 0..1023
            const int j    = idx & (m - 1);
            const int base = ((idx >> s2) << (s2 + 2)) + j;
            const float2 x0 = data[base];
            const float2 x1 = data[base + m];
            const float2 x2 = data[base + 2*m];
            const float2 x3 = data[base + 3*m];
            const float2 a  = cadd(x0, x2);
            const float2 b  = csub(x0, x2);
            const float2 c  = cadd(x1, x3);
            const float2 d  = csub(x1, x3);
            const float2 di = make_float2(d.y, -d.x);      // -i*d
            const float2 w1 = tw[j * step];
            const float2 w2 = cmul(w1, w1);
            const float2 w3 = cmul(w1, w2);
            data[base]       = cadd(a, c);
            data[base + m]   = cmul(cadd(b, di), w1);
            data[base + 2*m] = cmul(csub(a, c), w2);
            data[base + 3*m] = cmul(csub(b, di), w3);
        }
        __syncthreads();
    }
}

__device__ void fft4_inv(float2* data, const float2* tw, int tid) {
    #pragma unroll
    for (int s2 = 0; s2 <= 10; s2 += 2) {
        const int m    = 1 << s2;
        const int step = 1024 >> s2;
        #pragma unroll
        for (int t = 0; t < 2; t++) {
            const int idx  = tid + t * 512;
            const int j    = idx & (m - 1);
            const int base = ((idx >> s2) << (s2 + 2)) + j;
            float2 w1 = tw[j * step];
            w1.y = -w1.y;                                   // conj
            const float2 w2 = cmul(w1, w1);
            const float2 w3 = cmul(w1, w2);
            const float2 z0 = data[base];
            const float2 z1 = cmul(data[base + m],   w1);
            const float2 z2 = cmul(data[base + 2*m], w2);
            const float2 z3 = cmul(data[base + 3*m], w3);
            const float2 s02 = cadd(z0, z2);
            const float2 d02 = csub(z0, z2);
            const float2 s13 = cadd(z1, z3);
            const float2 d13 = csub(z1, z3);
            data[base]       = cadd(s02, s13);
            data[base + 2*m] = csub(s02, s13);
            data[base + m]   = make_float2(d02.x - d13.y, d02.y + d13.x);
            data[base + 3*m] = make_float2(d02.x + d13.y, d02.y - d13.x);
        }
        __syncthreads();
    }
}

// base-4 digit reversal of a 12-bit index (involution)
__device__ __forceinline__ int rev4_12(int x) {
    const int r = (int)(__brev((unsigned)x) >> 20);         // bitrev12
    return ((r & 0x555) << 1) | ((r >> 1) & 0x555);         // swap adjacent bits
}

// =====================================================================
// FFT of filter k  ->  g_Kf (radix-4 digit-reversed order)
// =====================================================================
__global__ __launch_bounds__(512) void fftk_kernel() {
    __shared__ float2 data[NFFT];
    __shared__ float2 tw[NFFT/4];
    const int d = blockIdx.x;
    const int tid = threadIdx.x;
    copy_tw(tw, tid);
    #pragma unroll
    for (int i = tid; i < LL; i += 512) {
        data[i]      = make_float2(g_k[d*LL + i], 0.f);
        data[i + LL] = make_float2(0.f, 0.f);
    }
    __syncthreads();
    fft4_fwd(data, tw, tid);
    #pragma unroll
    for (int i = tid; i < NFFT; i += 512) g_Kf[(size_t)d*NFFT + i] = data[i];
}

// =====================================================================
// Prep: convert fp32 -> fp16 (same layout)
// =====================================================================
__global__ __launch_bounds__(256) void convert_kernel(
    const float* __restrict__ in, __half* __restrict__ out, int n4)
{
    const int i = blockIdx.x * 256 + threadIdx.x;
    if (i >= n4) return;
    const float4 v = reinterpret_cast<const float4*>(in)[i];
    reinterpret_cast<__half2*>(out)[i*2]   = __floats2half2_rn(v.x, v.y);
    reinterpret_cast<__half2*>(out)[i*2+1] = __floats2half2_rn(v.z, v.w);
}

// =====================================================================
// Prep: transpose [R][C] fp32 -> [C][R] fp16 hi/lo (weights)
// =====================================================================
__global__ __launch_bounds__(256) void transpose_split_kernel(
    const float* __restrict__ in, __half* __restrict__ oh,
    __half* __restrict__ ol, int R, int C)
{
    __shared__ float tile[32][33];
    const int r0 = blockIdx.y * 32, c0 = blockIdx.x * 32;
    const int tx = threadIdx.x & 31, ty = threadIdx.x >> 5;
    #pragma unroll
    for (int i = 0; i < 32; i += 8)
        tile[ty+i][tx] = in[(size_t)(r0+ty+i)*C + c0 + tx];
    __syncthreads();
    #pragma unroll
    for (int i = 0; i < 32; i += 8) {
        const float x = tile[tx][ty+i];
        const __half h = __float2half_rn(x);
        const __half l = __float2half_rn(x - __half2float(h));
        const size_t o = (size_t)(c0+ty+i)*R + r0 + tx;
        oh[o] = h;
        ol[o] = l;
    }
}

// =====================================================================
// Prep: transpose [b][R][C] fp32 -> [b][C][R] fp16 (activation y)
// =====================================================================
__global__ __launch_bounds__(256) void transpose_convert_kernel(
    const float* __restrict__ in, __half* __restrict__ out, int R, int C,
    size_t batchStride)
{
    __shared__ float tile[32][33];
    const int b  = blockIdx.z;
    const float* src = in + (size_t)b * batchStride;
    const int r0 = blockIdx.y * 32, c0 = blockIdx.x * 32;
    const int tx = threadIdx.x & 31, ty = threadIdx.x >> 5;
    #pragma unroll
    for (int i = 0; i < 32; i += 8)
        tile[ty+i][tx] = src[(size_t)(r0+ty+i)*C + c0 + tx];
    __syncthreads();
    #pragma unroll
    for (int i = 0; i < 32; i += 8) {
        const size_t o = (size_t)b*batchStride + (size_t)(c0+ty+i)*R + r0 + tx;
        out[o] = __float2half_rn(tile[tx][ty+i]);
    }
}

// =====================================================================
// mma.sync GEMM: C[M][N] = A[M][K] @ (Bh+Bl)[N][K]^T + bias
// A fp16; B fp16 hi/lo -> 2 mma passes. cp.async 3-stage pipeline,
// ONE __syncthreads per K-chunk (distance-2 prefetch).
// CTA tile 128x128, 8 warps (32m x 64n each), K-chunks of 32.
// =====================================================================
#define KB       32                   // K halves per chunk
#define AS_STRIDE 40                  // halves per smem row (32 data + 8 pad)
#define ARR_BYTES (128*AS_STRIDE*2)   // 10240 B per array
#define NSTAGE   3

__global__ __launch_bounds__(256, 2) void gemm_mma_kernel(
    const __half* __restrict__ A,
    const __half* __restrict__ Bh, const __half* __restrict__ Bl,
    const float* __restrict__ bias, float* __restrict__ C,
    int K, int N)
{
    // 3 stages x 3 arrays (A, BH, BL) x 10240 B = 92160 B
    __shared__ __align__(16) __half smbuf[NSTAGE*3*128*AS_STRIDE];
    const uint32_t smem_base = smem_u32(smbuf);

    const int tid  = threadIdx.x;
    const int wid  = tid >> 5;
    const int lane = tid & 31;
    const int m0 = blockIdx.y * 128;
    const int n0 = blockIdx.x * 128;
    const int wm = (wid & 3) * 32;   // warp m offset in tile
    const int wn = (wid >> 2) * 64;  // warp n offset in tile

    // copy mapping: 512 16B-segments per array, 2 per thread
    const int r0s = tid >> 2;
    const int p0s = tid & 3;

    // ldmatrix per-lane offsets (bytes, within one array)
    const int arow  = wm + (lane & 15);
    const uint32_t aoffs = (uint32_t)arow * (AS_STRIDE*2) + (uint32_t)(lane >> 4) * 16;
    const int brow  = wn + (lane & 7) + ((lane >> 4) & 1) * 8;
    const uint32_t boffs = (uint32_t)brow * (AS_STRIDE*2) + (uint32_t)((lane >> 3) & 1) * 16;

    float acc[2][8][4];
    #pragma unroll
    for (int i = 0; i < 2; i++)
        #pragma unroll
        for (int j = 0; j < 8; j++)
            #pragma unroll
            for (int q = 0; q < 4; q++) acc[i][j][q] = 0.f;

    const int NKB = K / KB;   // 24

    #define ISSUE_CHUNK(k0, st) do {                                                 \
        const uint32_t sbase = smem_base + (uint32_t)(st)*3*ARR_BYTES;               \
        _Pragma("unroll")                                                            \
        for (int t = 0; t < 2; t++) {                                                \
            const int row  = r0s + t*64;                                             \
            const int kk   = (k0) + p0s*8;                                           \
            const uint32_t dst = sbase + (uint32_t)row*(AS_STRIDE*2) + p0s*16;       \
            CP_ASYNC16(dst,               (const char*)(A  + (size_t)(m0+row)*K + kk)); \
            CP_ASYNC16(dst +   ARR_BYTES, (const char*)(Bh + (size_t)(n0+row)*K + kk)); \
            CP_ASYNC16(dst + 2*ARR_BYTES, (const char*)(Bl + (size_t)(n0+row)*K + kk)); \
        }                                                                            \
    } while (0)

    // prologue: chunks 0 and 1 in flight (one commit group each)
    ISSUE_CHUNK(0, 0);
    CP_COMMIT();
    if (NKB > 1) ISSUE_CHUNK(KB, 1);
    CP_COMMIT();

    int st = 0;
    for (int kb = 0; kb < NKB; kb++) {
        cp_wait<1>();          // chunk kb complete (kb+1 may be pending)
        __syncthreads();       // data-ready + stage-(kb-1)-read-done guard

        const uint32_t bA  = smem_base + (uint32_t)st*3*ARR_BYTES;
        const uint32_t bBh = bA +   ARR_BYTES;
        const uint32_t bBl = bA + 2*ARR_BYTES;

        #pragma unroll
        for (int ks = 0; ks < 2; ks++) {
            const uint32_t ko = (uint32_t)ks * 32;   // +16 halves = 32 bytes
            uint32_t ah[2][4];
            ldmatrix_x4(ah[0][0], ah[0][1], ah[0][2], ah[0][3], bA + aoffs + ko);
            ldmatrix_x4(ah[1][0], ah[1][1], ah[1][2], ah[1][3], bA + aoffs + ko + 16*(AS_STRIDE*2));

            #pragma unroll
            for (int p = 0; p < 4; p++) {
                uint32_t bh0, bh1, bh2, bh3, bl0, bl1, bl2, bl3;
                const uint32_t bo = boffs + ko + (uint32_t)p * (16*AS_STRIDE*2);
                ldmatrix_x4(bh0, bh1, bh2, bh3, bBh + bo);
                ldmatrix_x4(bl0, bl1, bl2, bl3, bBl + bo);
                #pragma unroll
                for (int mt = 0; mt < 2; mt++) {
                    mma16816(acc[mt][2*p],   ah[mt][0], ah[mt][1], ah[mt][2], ah[mt][3], bh0, bh1);
                    mma16816(acc[mt][2*p],   ah[mt][0], ah[mt][1], ah[mt][2], ah[mt][3], bl0, bl1);
                    mma16816(acc[mt][2*p+1], ah[mt][0], ah[mt][1], ah[mt][2], ah[mt][3], bh2, bh3);
                    mma16816(acc[mt][2*p+1], ah[mt][0], ah[mt][1], ah[mt][2], ah[mt][3], bl2, bl3);
                }
            }
        }

        // distance-2 prefetch into stage (st+2)%3 (read finished at kb-1,
        // guarded by this iteration's __syncthreads). Always commit one
        // group (possibly empty) to keep cp_wait<1> semantics exact.
        if (kb + 2 < NKB) {
            const int st2 = (st + 2 >= NSTAGE) ? st + 2 - NSTAGE : st + 2;
            ISSUE_CHUNK((kb + 2) * KB, st2);
        }
        CP_COMMIT();

        st = (st + 1 == NSTAGE) ? 0 : st + 1;
    }
    #undef ISSUE_CHUNK

    // epilogue: fragment layout -> gmem with bias
    const int crow = lane >> 2;
    const int ccol = (lane & 3) * 2;
    #pragma unroll
    for (int mt = 0; mt < 2; mt++) {
        const int mbase = m0 + wm + mt*16 + crow;
        #pragma unroll
        for (int nt = 0; nt < 8; nt++) {
            const int n = n0 + wn + nt*8 + ccol;
            const float b0 = bias[n], b1 = bias[n+1];
            float2 r0 = make_float2(acc[mt][nt][0] + b0, acc[mt][nt][1] + b1);
            float2 r1 = make_float2(acc[mt][nt][2] + b0, acc[mt][nt][3] + b1);
            *reinterpret_cast<float2*>(&C[(size_t)mbase*N + n])     = r0;
            *reinterpret_cast<float2*>(&C[(size_t)(mbase+8)*N + n]) = r1;
        }
    }
}

// =====================================================================
// depthwise conv-4 (causal) + gating + transpose
// =====================================================================
__global__ __launch_bounds__(256) void convgate_kernel(
    const float* __restrict__ x1_s, const float* __restrict__ x2_s,
    const float* __restrict__ v_s,
    const float* __restrict__ x1_sb, const float* __restrict__ x2_sb,
    const float* __restrict__ v_sb)
{
    __shared__ float sh1[35*33];
    __shared__ float sh2[35*33];
    __shared__ float shv[35*33];
    const int tid = threadIdx.x;
    const int d0 = blockIdx.x * 32;
    const int l0 = blockIdx.y * 32;
    const int b  = blockIdx.z;

    for (int idx = tid; idx < 35*32; idx += 256) {
        const int r  = idx >> 5;
        const int cc = idx & 31;
        const int lg = l0 - 3 + r;
        float v1 = 0.f, v2 = 0.f, vv = 0.f;
        if (lg >= 0) {
            const size_t rowbase = ((size_t)(b*LL + lg)) * N3D + d0 + cc;
            v1 = g_xbuf[rowbase];
            v2 = g_xbuf[rowbase + DD];
            vv = g_xbuf[rowbase + 2*DD];
        }
        sh1[r*33 + cc] = v1;
        sh2[r*33 + cc] = v2;
        shv[r*33 + cc] = vv;
    }
    __syncthreads();

    #pragma unroll
    for (int t = 0; t < 4; t++) {
        const int o  = tid + t*256;
        const int dd = o >> 5;
        const int ll = o & 31;
        const int d  = d0 + dd;
        float c1 = x1_sb[d], c2 = x2_sb[d], cv = v_sb[d];
        #pragma unroll
        for (int j = 0; j < 4; j++) {
            const int r = ll + j;
            c1 += x1_s[d*4 + j] * sh1[r*33 + dd];
            c2 += x2_s[d*4 + j] * sh2[r*33 + dd];
            cv += v_s [d*4 + j] * shv[r*33 + dd];
        }
        const size_t out = ((size_t)(b*DD + d)) * LL + l0 + ll;
        g_vg [out] = cv * c1;
        g_x2g[out] = c2;
    }
}

// =====================================================================
// packed two-channel radix-4 FFT convolution + D_bias + x2 gate
// =====================================================================
__global__ __launch_bounds__(512) void fftconv2_kernel(const float* __restrict__ D_bias) {
    __shared__ float2 data[NFFT];
    __shared__ float2 tw[NFFT/4];
    const int c   = blockIdx.x;          // 0..3071
    const int b   = c / (DD/2);
    const int d1  = (c % (DD/2)) * 2;
    const int d2  = d1 + 1;
    const int tid = threadIdx.x;
    const size_t ch1 = ((size_t)b*DD + d1) * LL;
    const size_t ch2 = ch1 + LL;

    copy_tw(tw, tid);
    float v1c[4], v2c[4];
    #pragma unroll
    for (int i = 0; i < 4; i++) {
        const int l = tid + i*512;
        const float v1 = g_vg[ch1 + l];
        const float v2 = g_vg[ch2 + l];
        v1c[i] = v1; v2c[i] = v2;
        data[l]      = make_float2(v1, v2);
        data[l + LL] = make_float2(0.f, 0.f);
    }
    __syncthreads();

    fft4_fwd(data, tw, tid);             // ends with __syncthreads()

    const float2* __restrict__ kf1 = &g_Kf[(size_t)d1 * NFFT];
    const float2* __restrict__ kf2 = &g_Kf[(size_t)d2 * NFFT];
    float2 Y[8];
    #pragma unroll
    for (int i = 0; i < 8; i++) {
        const int p = tid + i*512;
        const int f = rev4_12(p);
        const int q = rev4_12((NFFT - f) & (NFFT-1));
        const float2 Zp = data[p];
        const float2 Zq = data[q];
        const float2 V1 = make_float2(0.5f*(Zp.x + Zq.x), 0.5f*(Zp.y - Zq.y));
        const float2 V2 = make_float2(0.5f*(Zp.y + Zq.y), 0.5f*(Zq.x - Zp.x));
        const float2 C1 = cmul(V1, kf1[p]);
        const float2 C2 = cmul(V2, kf2[p]);
        Y[i] = make_float2(C1.x - C2.y, C1.y + C2.x);
    }
    __syncthreads();
    #pragma unroll
    for (int i = 0; i < 8; i++) data[tid + i*512] = Y[i];
    __syncthreads();

    fft4_inv(data, tw, tid);             // ends with __syncthreads()

    const float db1 = D_bias[d1];
    const float db2 = D_bias[d2];
    #pragma unroll
    for (int i = 0; i < 4; i++) {
        const int l = tid + i*512;
        const float y1 = data[l].x * (1.0f / (float)NFFT);
        const float y2 = data[l].y * (1.0f / (float)NFFT);
        g_ybT[ch1 + l] = (y1 + v1c[i] * db1) * g_x2g[ch1 + l];
        g_ybT[ch2 + l] = (y2 + v2c[i] * db2) * g_x2g[ch2 + l];
    }
}

// =====================================================================
// launch  (gemm1 is deliberately the 4th launch: ncu captures launch #4)
// =====================================================================
extern "C" void kernel_launch(void* const* d_in, const int* in_sizes, int n_in,
                              void* d_out, int out_size) {
    const float* u      = (const float*)d_in[0];
    const float* in_W   = (const float*)d_in[1];
    const float* in_b   = (const float*)d_in[2];
    const float* out_W  = (const float*)d_in[3];
    const float* out_b  = (const float*)d_in[4];
    const float* x1_s   = (const float*)d_in[5];
    const float* x2_s   = (const float*)d_in[6];
    const float* v_s    = (const float*)d_in[7];
    const float* x1_sb  = (const float*)d_in[8];
    const float* x2_sb  = (const float*)d_in[9];
    const float* v_sb   = (const float*)d_in[10];
    const float* D_bias = (const float*)d_in[11];
    const float* z      = (const float*)d_in[12];
    const float* sfreq  = (const float*)d_in[13];
    const float* eo_mat = (const float*)d_in[14];
    const float* eo_b   = (const float*)d_in[15];
    const float* oo1    = (const float*)d_in[16];
    const float* oo1_b  = (const float*)d_in[17];
    const float* oo2    = (const float*)d_in[18];
    const float* oo2_b  = (const float*)d_in[19];
    const float* oh     = (const float*)d_in[20];
    float* out = (float*)d_out;

    float *xbuf, *ybT;
    __half *uh, *wh, *wl, *woh, *wol, *yh;
    cudaGetSymbolAddress((void**)&xbuf, g_xbuf);
    cudaGetSymbolAddress((void**)&ybT,  g_ybT);
    cudaGetSymbolAddress((void**)&uh,  g_uh);
    cudaGetSymbolAddress((void**)&wh,  g_wh);
    cudaGetSymbolAddress((void**)&wl,  g_wl);
    cudaGetSymbolAddress((void**)&woh, g_woh);
    cudaGetSymbolAddress((void**)&wol, g_wol);
    cudaGetSymbolAddress((void**)&yh,  g_yh);

    // (1-3) GEMM1 operand preps
    convert_kernel<<<(MM*DD/4 + 255)/256, 256>>>(u, uh, MM*DD/4);
    transpose_split_kernel<<<dim3(N3D/32, DD/32), 256>>>(in_W,  wh,  wl,  DD, N3D);
    transpose_split_kernel<<<dim3(DD/32,  DD/32), 256>>>(out_W, woh, wol, DD, DD);

    // (4) GEMM1: [16384 x 768] @ [768 x 2304]  <- ncu-captured launch
    gemm_mma_kernel<<<dim3(N3D/128, MM/128), 256>>>(uh, wh, wl, in_b, xbuf, DD, N3D);

    // (5-7) filter chain (independent of GEMM1)
    twinit_kernel<<<2, 512>>>();
    filter_kernel<<<LL/16, 128>>>(z, sfreq, eo_mat, eo_b, oo1, oo1_b, oo2, oo2_b, oh);
    fftk_kernel<<<DD, 512>>>();

    // (8-9) conv/gate + packed radix-4 FFT convolution
    convgate_kernel<<<dim3(DD/32, LL/32, BB), 256>>>(x1_s, x2_s, v_s, x1_sb, x2_sb, v_sb);
    fftconv2_kernel<<<BB*DD/2, 512>>>(D_bias);

    // (10) y -> [(b,l)][d] fp16
    transpose_convert_kernel<<<dim3(LL/32, DD/32, BB), 256>>>(
        ybT, yh, DD, LL, (size_t)DD*LL);

    // (11) GEMM2: [16384 x 768] @ [768 x 768]
    gemm_mma_kernel<<<dim3(DD/128, MM/128), 256>>>(yh, woh, wol, out_b, out, DD, DD);
}